// round 1
// baseline (speedup 1.0000x reference)
#include <cuda_runtime.h>
#include <cuda_bf16.h>
#include <math.h>

// Problem constants
#define T_SEQ 2048
#define H_DIM 2048
#define NH 32
#define NKV 8
#define HD 64
#define SW 128
#define QM 4              // NH / NKV
#define QKVD 3072         // HD*(NH+2*NKV)
#define EPS 1e-5f

// Scratch (device globals; no allocation allowed)
__device__ float g_normed[T_SEQ * H_DIM];
__device__ float g_qkv[T_SEQ * QKVD];
__device__ float g_attn[T_SEQ * H_DIM];

// ---------------------------------------------------------------------------
// Kernel 1: RMSNorm per row
// ---------------------------------------------------------------------------
__global__ void rmsnorm_kernel(const float* __restrict__ x,
                               const float* __restrict__ scale,
                               float* __restrict__ out) {
    __shared__ float red[256];
    int row = blockIdx.x;
    int tid = threadIdx.x;
    const float4* xr = (const float4*)(x + (size_t)row * H_DIM);
    float4 v0 = xr[tid];
    float4 v1 = xr[tid + 256];
    float ss = v0.x * v0.x + v0.y * v0.y + v0.z * v0.z + v0.w * v0.w
             + v1.x * v1.x + v1.y * v1.y + v1.z * v1.z + v1.w * v1.w;
    red[tid] = ss;
    __syncthreads();
    for (int s = 128; s > 0; s >>= 1) {
        if (tid < s) red[tid] += red[tid + s];
        __syncthreads();
    }
    float inv = rsqrtf(red[0] * (1.0f / H_DIM) + EPS);
    const float4* sc = (const float4*)scale;
    float4 s0 = sc[tid], s1 = sc[tid + 256];
    float4 o0, o1;
    o0.x = v0.x * inv * s0.x; o0.y = v0.y * inv * s0.y;
    o0.z = v0.z * inv * s0.z; o0.w = v0.w * inv * s0.w;
    o1.x = v1.x * inv * s1.x; o1.y = v1.y * inv * s1.y;
    o1.z = v1.z * inv * s1.z; o1.w = v1.w * inv * s1.w;
    float4* outr = (float4*)(out + (size_t)row * H_DIM);
    outr[tid] = o0;
    outr[tid + 256] = o1;
}

// ---------------------------------------------------------------------------
// Kernel 2/5: fp32 tiled GEMM  C = A@B + bias (+ resid)
// BM=BN=128, BK=16, 256 threads, 8x8 per thread
// ---------------------------------------------------------------------------
template <bool RESID>
__global__ __launch_bounds__(256, 2)
void gemm128(const float* __restrict__ A, const float* __restrict__ B,
             const float* __restrict__ bias, const float* __restrict__ resid,
             float* __restrict__ C, int M, int N, int K) {
    __shared__ float As[16][128];
    __shared__ float Bs[16][128];

    int tid = threadIdx.x;
    int tx = tid & 15;      // 0..15 -> N
    int ty = tid >> 4;      // 0..15 -> M
    int aRow0 = blockIdx.y * 128;
    int bCol0 = blockIdx.x * 128;

    float acc[8][8];
#pragma unroll
    for (int i = 0; i < 8; i++)
#pragma unroll
        for (int j = 0; j < 8; j++) acc[i][j] = 0.0f;

    for (int k0 = 0; k0 < K; k0 += 16) {
        // load A tile (128x16) transposed into As
#pragma unroll
        for (int i = 0; i < 2; i++) {
            int v = tid * 2 + i;            // 0..511
            int r = v >> 2;                 // 0..127
            int c4 = (v & 3) * 4;           // 0,4,8,12
            float4 a = *(const float4*)&A[(size_t)(aRow0 + r) * K + k0 + c4];
            As[c4 + 0][r] = a.x;
            As[c4 + 1][r] = a.y;
            As[c4 + 2][r] = a.z;
            As[c4 + 3][r] = a.w;
            // load B tile (16x128)
            int rb = v >> 5;                // 0..15
            int cb = (v & 31) * 4;          // 0..124
            *(float4*)&Bs[rb][cb] = *(const float4*)&B[(size_t)(k0 + rb) * N + bCol0 + cb];
        }
        __syncthreads();
#pragma unroll
        for (int k = 0; k < 16; k++) {
            float ra[8], rb[8];
            *(float4*)&ra[0] = *(float4*)&As[k][ty * 8];
            *(float4*)&ra[4] = *(float4*)&As[k][ty * 8 + 4];
            *(float4*)&rb[0] = *(float4*)&Bs[k][tx * 8];
            *(float4*)&rb[4] = *(float4*)&Bs[k][tx * 8 + 4];
#pragma unroll
            for (int i = 0; i < 8; i++)
#pragma unroll
                for (int j = 0; j < 8; j++) acc[i][j] = fmaf(ra[i], rb[j], acc[i][j]);
        }
        __syncthreads();
    }

    int row0 = aRow0 + ty * 8;
    int col0 = bCol0 + tx * 8;
#pragma unroll
    for (int i = 0; i < 8; i++) {
#pragma unroll
        for (int jv = 0; jv < 2; jv++) {
            int col = col0 + jv * 4;
            float4 b = *(const float4*)&bias[col];
            float4 r;
            r.x = acc[i][jv * 4 + 0] + b.x;
            r.y = acc[i][jv * 4 + 1] + b.y;
            r.z = acc[i][jv * 4 + 2] + b.z;
            r.w = acc[i][jv * 4 + 3] + b.w;
            if (RESID) {
                float4 rs = *(const float4*)&resid[(size_t)(row0 + i) * N + col];
                r.x += rs.x; r.y += rs.y; r.z += rs.z; r.w += rs.w;
            }
            *(float4*)&C[(size_t)(row0 + i) * N + col] = r;
        }
    }
}

// ---------------------------------------------------------------------------
// Kernel 3: RoPE in place on q (heads 0..31) and k (heads 32..39)
// ---------------------------------------------------------------------------
__global__ void rope_kernel(const float* __restrict__ cosT,
                            const float* __restrict__ sinT) {
    int idx = blockIdx.x * blockDim.x + threadIdx.x;
    if (idx >= T_SEQ * 40 * 32) return;
    int d = idx & 31;
    int rest = idx >> 5;
    int head = rest % 40;
    int t = rest / 40;
    float c = cosT[t * 32 + d];
    float s = sinT[t * 32 + d];
    float* p = g_qkv + (size_t)t * QKVD + head * 64 + d;
    float x1 = p[0];
    float x2 = p[32];
    p[0] = x1 * c - x2 * s;
    p[32] = x2 * c + x1 * s;
}

// ---------------------------------------------------------------------------
// Kernel 4: sliding-window GQA attention with sinks.
// Block = (16 queries) x (1 kv head, all 4 q-heads). 256 threads.
// Keys in [max(0,qstart-128), qstart+15] -> NKEY <= 144.
// ---------------------------------------------------------------------------
#define TQ 16
#define NKMAX 144
// smem floats: Q 64*65 + K 144*65 + V 144*68 + S 64*145
#define SM_Q 0
#define SM_K (64 * 65)
#define SM_V (SM_K + 144 * 65)
#define SM_S (SM_V + 144 * 68)
#define SM_TOTAL (SM_S + 64 * 145)

__global__ void attn_kernel(const float* __restrict__ sinks) {
    extern __shared__ float sm[];
    float* Qs = sm + SM_Q;   // [64][65]  row = m*16+qi
    float* Ks = sm + SM_K;   // [144][65]
    float* Vs = sm + SM_V;   // [144][68]
    float* Ss = sm + SM_S;   // [64][145]

    int qb = blockIdx.x;
    int n = blockIdx.y;
    int qstart = qb * TQ;
    int kmin = qstart - SW; if (kmin < 0) kmin = 0;
    int nkey = qstart + TQ - kmin;   // <= 144
    int tid = threadIdx.x;

    // load Q (64 rows x 64 dims)
    for (int v = tid; v < 64 * 16; v += 256) {
        int row = v >> 4;
        int d4 = (v & 15) * 4;
        int m = row >> 4, qi = row & 15;
        float4 q = *(const float4*)&g_qkv[(size_t)(qstart + qi) * QKVD + n * 256 + m * 64 + d4];
        Qs[row * 65 + d4 + 0] = q.x;
        Qs[row * 65 + d4 + 1] = q.y;
        Qs[row * 65 + d4 + 2] = q.z;
        Qs[row * 65 + d4 + 3] = q.w;
    }
    // load K/V tiles
    for (int v = tid; v < nkey * 16; v += 256) {
        int r = v >> 4;
        int d4 = (v & 15) * 4;
        int kg = kmin + r;
        float4 kk = *(const float4*)&g_qkv[(size_t)kg * QKVD + 2048 + n * 64 + d4];
        Ks[r * 65 + d4 + 0] = kk.x;
        Ks[r * 65 + d4 + 1] = kk.y;
        Ks[r * 65 + d4 + 2] = kk.z;
        Ks[r * 65 + d4 + 3] = kk.w;
        float4 vv = *(const float4*)&g_qkv[(size_t)kg * QKVD + 2560 + n * 64 + d4];
        *(float4*)&Vs[r * 68 + d4] = vv;
    }
    __syncthreads();

    int tx = tid & 15, ty = tid >> 4;
    int r0 = ty * 4;          // 4 rows per thread
    int k0 = tx * 9;          // 9 keys per thread

    // S = Q @ K^T
    float acc[4][9];
#pragma unroll
    for (int i = 0; i < 4; i++)
#pragma unroll
        for (int j = 0; j < 9; j++) acc[i][j] = 0.0f;
#pragma unroll 8
    for (int d = 0; d < 64; d++) {
        float qa[4], kb[9];
#pragma unroll
        for (int i = 0; i < 4; i++) qa[i] = Qs[(r0 + i) * 65 + d];
#pragma unroll
        for (int j = 0; j < 9; j++) kb[j] = Ks[(k0 + j) * 65 + d];
#pragma unroll
        for (int i = 0; i < 4; i++)
#pragma unroll
            for (int j = 0; j < 9; j++) acc[i][j] = fmaf(qa[i], kb[j], acc[i][j]);
    }
    // mask + scale, write to Ss
#pragma unroll
    for (int j = 0; j < 9; j++) {
        int key = k0 + j;
        if (key < nkey) {
            int kg = kmin + key;
#pragma unroll
            for (int i = 0; i < 4; i++) {
                int row = r0 + i;
                int qg = qstart + (row & 15);
                float s;
                if (kg <= qg && (qg - kg) <= SW) s = acc[i][j] * 0.125f;
                else s = -1e30f;
                Ss[row * 145 + key] = s;
            }
        }
    }
    __syncthreads();

    // softmax with sink: warp w handles rows w*8..w*8+7
    int wid = tid >> 5, lane = tid & 31;
    for (int rr = 0; rr < 8; rr++) {
        int row = wid * 8 + rr;
        int m = row >> 4;
        float s0 = sinks[n * QM + m];
        float vmax = -1e30f;
        for (int k = lane; k < nkey; k += 32) vmax = fmaxf(vmax, Ss[row * 145 + k]);
#pragma unroll
        for (int off = 16; off > 0; off >>= 1)
            vmax = fmaxf(vmax, __shfl_xor_sync(0xffffffffu, vmax, off));
        vmax = fmaxf(vmax, s0);
        float vsum = 0.0f;
        for (int k = lane; k < nkey; k += 32) {
            float e = __expf(Ss[row * 145 + k] - vmax);
            Ss[row * 145 + k] = e;
            vsum += e;
        }
#pragma unroll
        for (int off = 16; off > 0; off >>= 1)
            vsum += __shfl_xor_sync(0xffffffffu, vsum, off);
        vsum += __expf(s0 - vmax);
        float inv = 1.0f / vsum;
        for (int k = lane; k < nkey; k += 32) Ss[row * 145 + k] *= inv;
    }
    __syncthreads();

    // O = W @ V : thread handles rows r0..r0+3, cols tx*4..tx*4+3
    int c0 = tx * 4;
    float o[4][4];
#pragma unroll
    for (int i = 0; i < 4; i++)
#pragma unroll
        for (int j = 0; j < 4; j++) o[i][j] = 0.0f;
    for (int k = 0; k < nkey; k++) {
        float4 vv = *(float4*)&Vs[k * 68 + c0];
        float ws[4];
#pragma unroll
        for (int i = 0; i < 4; i++) ws[i] = Ss[(r0 + i) * 145 + k];
#pragma unroll
        for (int i = 0; i < 4; i++) {
            o[i][0] = fmaf(ws[i], vv.x, o[i][0]);
            o[i][1] = fmaf(ws[i], vv.y, o[i][1]);
            o[i][2] = fmaf(ws[i], vv.z, o[i][2]);
            o[i][3] = fmaf(ws[i], vv.w, o[i][3]);
        }
    }
#pragma unroll
    for (int i = 0; i < 4; i++) {
        int row = r0 + i;
        int t = qstart + (row & 15);
        int m = row >> 4;
        int col = n * 256 + m * 64 + c0;
        float4 r;
        r.x = o[i][0]; r.y = o[i][1]; r.z = o[i][2]; r.w = o[i][3];
        *(float4*)&g_attn[(size_t)t * H_DIM + col] = r;
    }
}

// ---------------------------------------------------------------------------
// Launch
// ---------------------------------------------------------------------------
extern "C" void kernel_launch(void* const* d_in, const int* in_sizes, int n_in,
                              void* d_out, int out_size) {
    const float* x       = (const float*)d_in[0];
    const float* scale   = (const float*)d_in[1];
    const float* sinks   = (const float*)d_in[2];
    const float* qkvW    = (const float*)d_in[3];
    const float* qkvB    = (const float*)d_in[4];
    const float* outW    = (const float*)d_in[5];
    const float* outB    = (const float*)d_in[6];
    const float* cosT    = (const float*)d_in[7];
    const float* sinT    = (const float*)d_in[8];
    float* out = (float*)d_out;

    float *p_normed, *p_qkv, *p_attn;
    cudaGetSymbolAddress((void**)&p_normed, g_normed);
    cudaGetSymbolAddress((void**)&p_qkv, g_qkv);
    cudaGetSymbolAddress((void**)&p_attn, g_attn);

    // 1. RMSNorm
    rmsnorm_kernel<<<T_SEQ, 256>>>(x, scale, p_normed);

    // 2. QKV GEMM: [2048,2048] @ [2048,3072] + bias
    {
        dim3 grid(QKVD / 128, T_SEQ / 128);
        gemm128<false><<<grid, 256>>>(p_normed, qkvW, qkvB, nullptr, p_qkv,
                                      T_SEQ, QKVD, H_DIM);
    }

    // 3. RoPE on q + k
    {
        int total = T_SEQ * 40 * 32;
        rope_kernel<<<(total + 255) / 256, 256>>>(cosT, sinT);
    }

    // 4. Attention
    {
        cudaFuncSetAttribute(attn_kernel, cudaFuncAttributeMaxDynamicSharedMemorySize,
                             SM_TOTAL * (int)sizeof(float));
        dim3 grid(T_SEQ / TQ, NKV);
        attn_kernel<<<grid, 256, SM_TOTAL * sizeof(float)>>>(sinks);
    }

    // 5. Output projection + residual
    {
        dim3 grid(H_DIM / 128, T_SEQ / 128);
        gemm128<true><<<grid, 256>>>(p_attn, outW, outB, x, out,
                                     T_SEQ, H_DIM, H_DIM);
    }
}

// round 4
// speedup vs baseline: 1.8998x; 1.8998x over previous
#include <cuda_runtime.h>
#include <cuda_bf16.h>
#include <math.h>

// Problem constants
#define T_SEQ 2048
#define H_DIM 2048
#define NH 32
#define NKV 8
#define HD 64
#define SW 128
#define QM 4              // NH / NKV
#define QKVD 3072         // HD*(NH+2*NKV)
#define EPS 1e-5f

// Scratch (device globals; no allocation allowed)
__device__ float g_normed[T_SEQ * H_DIM];
__device__ float g_qkv[T_SEQ * QKVD];
__device__ float g_attn[T_SEQ * H_DIM];

// ---------------------------------------------------------------------------
// Kernel 1: RMSNorm per row
// ---------------------------------------------------------------------------
__global__ void rmsnorm_kernel(const float* __restrict__ x,
                               const float* __restrict__ scale,
                               float* __restrict__ out) {
    __shared__ float red[256];
    int row = blockIdx.x;
    int tid = threadIdx.x;
    const float4* xr = (const float4*)(x + (size_t)row * H_DIM);
    float4 v0 = xr[tid];
    float4 v1 = xr[tid + 256];
    float ss = v0.x * v0.x + v0.y * v0.y + v0.z * v0.z + v0.w * v0.w
             + v1.x * v1.x + v1.y * v1.y + v1.z * v1.z + v1.w * v1.w;
    red[tid] = ss;
    __syncthreads();
    for (int s = 128; s > 0; s >>= 1) {
        if (tid < s) red[tid] += red[tid + s];
        __syncthreads();
    }
    float inv = rsqrtf(red[0] * (1.0f / H_DIM) + EPS);
    const float4* sc = (const float4*)scale;
    float4 s0 = sc[tid], s1 = sc[tid + 256];
    float4 o0, o1;
    o0.x = v0.x * inv * s0.x; o0.y = v0.y * inv * s0.y;
    o0.z = v0.z * inv * s0.z; o0.w = v0.w * inv * s0.w;
    o1.x = v1.x * inv * s1.x; o1.y = v1.y * inv * s1.y;
    o1.z = v1.z * inv * s1.z; o1.w = v1.w * inv * s1.w;
    float4* outr = (float4*)(out + (size_t)row * H_DIM);
    outr[tid] = o0;
    outr[tid + 256] = o1;
}

// ---------------------------------------------------------------------------
// Tensor-core GEMM with 3xBF16 split for fp32-class accuracy.
// C = A@B + bias (+resid).  BM=BN=128, BK=32, 256 threads (8 warps, 4x2).
// A smem: [m][k] pad 40 (conflict-free 32b frag loads)
// B smem: [k][n] pad 136 (conflict-free 16b frag loads)
// ---------------------------------------------------------------------------
#define APAD 40
#define BPAD 136

__device__ __forceinline__ unsigned short bf_bits(float x) {
    __nv_bfloat16 h = __float2bfloat16(x);
    return *reinterpret_cast<unsigned short*>(&h);
}
__device__ __forceinline__ float bf_val(unsigned short u) {
    __nv_bfloat16 h = *reinterpret_cast<__nv_bfloat16*>(&u);
    return __bfloat162float(h);
}

__device__ __forceinline__ void mma16816(float* c, const unsigned* a, const unsigned* b) {
    asm volatile(
        "mma.sync.aligned.m16n8k16.row.col.f32.bf16.bf16.f32 "
        "{%0,%1,%2,%3}, {%4,%5,%6,%7}, {%8,%9}, {%0,%1,%2,%3};\n"
        : "+f"(c[0]), "+f"(c[1]), "+f"(c[2]), "+f"(c[3])
        : "r"(a[0]), "r"(a[1]), "r"(a[2]), "r"(a[3]), "r"(b[0]), "r"(b[1]));
}

template <bool RESID>
__global__ __launch_bounds__(256, 2)
void gemm_mma(const float* __restrict__ A, const float* __restrict__ B,
              const float* __restrict__ bias, const float* __restrict__ resid,
              float* __restrict__ C, int M, int N, int K) {
    __shared__ unsigned short AsHi[128 * APAD];
    __shared__ unsigned short AsLo[128 * APAD];
    __shared__ unsigned short BsHi[32 * BPAD];
    __shared__ unsigned short BsLo[32 * BPAD];

    int tid = threadIdx.x;
    int lane = tid & 31;
    int wid = tid >> 5;
    int warp_m = wid & 3;     // 4 warps along M (32 rows each)
    int warp_n = wid >> 2;    // 2 warps along N (64 cols each)

    int row0 = blockIdx.y * 128;
    int col0 = blockIdx.x * 128;

    float acc[2][8][4];
#pragma unroll
    for (int i = 0; i < 2; i++)
#pragma unroll
        for (int j = 0; j < 8; j++)
#pragma unroll
            for (int l = 0; l < 4; l++) acc[i][j][l] = 0.0f;

    for (int k0 = 0; k0 < K; k0 += 32) {
        // ---- load A tile (128x32 fp32) -> hi/lo bf16 ----
#pragma unroll
        for (int i = 0; i < 4; i++) {
            int v = tid + i * 256;
            int r = v >> 3;           // 0..127
            int kq = (v & 7) * 4;     // 0..28
            float4 a = *(const float4*)&A[(size_t)(row0 + r) * K + k0 + kq];
            unsigned short h0 = bf_bits(a.x), h1 = bf_bits(a.y);
            unsigned short h2 = bf_bits(a.z), h3 = bf_bits(a.w);
            unsigned short l0 = bf_bits(a.x - bf_val(h0));
            unsigned short l1 = bf_bits(a.y - bf_val(h1));
            unsigned short l2 = bf_bits(a.z - bf_val(h2));
            unsigned short l3 = bf_bits(a.w - bf_val(h3));
            uint2 ph = make_uint2((unsigned)h0 | ((unsigned)h1 << 16),
                                  (unsigned)h2 | ((unsigned)h3 << 16));
            uint2 pl = make_uint2((unsigned)l0 | ((unsigned)l1 << 16),
                                  (unsigned)l2 | ((unsigned)l3 << 16));
            *(uint2*)&AsHi[r * APAD + kq] = ph;
            *(uint2*)&AsLo[r * APAD + kq] = pl;
        }
        // ---- load B tile (32x128 fp32) -> hi/lo bf16, natural [k][n] ----
#pragma unroll
        for (int i = 0; i < 4; i++) {
            int v = tid + i * 256;
            int k = v >> 5;            // 0..31
            int n4 = (v & 31) * 4;     // 0..124
            float4 b = *(const float4*)&B[(size_t)(k0 + k) * N + col0 + n4];
            unsigned short h0 = bf_bits(b.x), h1 = bf_bits(b.y);
            unsigned short h2 = bf_bits(b.z), h3 = bf_bits(b.w);
            unsigned short l0 = bf_bits(b.x - bf_val(h0));
            unsigned short l1 = bf_bits(b.y - bf_val(h1));
            unsigned short l2 = bf_bits(b.z - bf_val(h2));
            unsigned short l3 = bf_bits(b.w - bf_val(h3));
            uint2 ph = make_uint2((unsigned)h0 | ((unsigned)h1 << 16),
                                  (unsigned)h2 | ((unsigned)h3 << 16));
            uint2 pl = make_uint2((unsigned)l0 | ((unsigned)l1 << 16),
                                  (unsigned)l2 | ((unsigned)l3 << 16));
            *(uint2*)&BsHi[k * BPAD + n4] = ph;
            *(uint2*)&BsLo[k * BPAD + n4] = pl;
        }
        __syncthreads();

#pragma unroll
        for (int ks = 0; ks < 32; ks += 16) {
            // A fragments (hi and lo) for both m-tiles
            unsigned ah[2][4], al[2][4];
            int kk = ks + (lane & 3) * 2;
#pragma unroll
            for (int mt = 0; mt < 2; mt++) {
                int row = warp_m * 32 + mt * 16 + (lane >> 2);
                ah[mt][0] = *(const unsigned*)&AsHi[row * APAD + kk];
                ah[mt][1] = *(const unsigned*)&AsHi[(row + 8) * APAD + kk];
                ah[mt][2] = *(const unsigned*)&AsHi[row * APAD + kk + 8];
                ah[mt][3] = *(const unsigned*)&AsHi[(row + 8) * APAD + kk + 8];
                al[mt][0] = *(const unsigned*)&AsLo[row * APAD + kk];
                al[mt][1] = *(const unsigned*)&AsLo[(row + 8) * APAD + kk];
                al[mt][2] = *(const unsigned*)&AsLo[row * APAD + kk + 8];
                al[mt][3] = *(const unsigned*)&AsLo[(row + 8) * APAD + kk + 8];
            }
#pragma unroll
            for (int nh = 0; nh < 8; nh++) {
                int n = warp_n * 64 + nh * 8 + (lane >> 2);
                unsigned bh[2], bl[2];
                bh[0] = (unsigned)BsHi[kk * BPAD + n] |
                        ((unsigned)BsHi[(kk + 1) * BPAD + n] << 16);
                bh[1] = (unsigned)BsHi[(kk + 8) * BPAD + n] |
                        ((unsigned)BsHi[(kk + 9) * BPAD + n] << 16);
                bl[0] = (unsigned)BsLo[kk * BPAD + n] |
                        ((unsigned)BsLo[(kk + 1) * BPAD + n] << 16);
                bl[1] = (unsigned)BsLo[(kk + 8) * BPAD + n] |
                        ((unsigned)BsLo[(kk + 9) * BPAD + n] << 16);
#pragma unroll
                for (int mt = 0; mt < 2; mt++) {
                    mma16816(acc[mt][nh], ah[mt], bh);
                    mma16816(acc[mt][nh], ah[mt], bl);
                    mma16816(acc[mt][nh], al[mt], bh);
                }
            }
        }
        __syncthreads();
    }

    // ---- epilogue: bias (+resid) ----
#pragma unroll
    for (int mt = 0; mt < 2; mt++) {
        int r0 = row0 + warp_m * 32 + mt * 16 + (lane >> 2);
        int r1 = r0 + 8;
#pragma unroll
        for (int nh = 0; nh < 8; nh++) {
            int cc = col0 + warp_n * 64 + nh * 8 + (lane & 3) * 2;
            float b0 = bias[cc], b1 = bias[cc + 1];
            float2 v0, v1;
            v0.x = acc[mt][nh][0] + b0; v0.y = acc[mt][nh][1] + b1;
            v1.x = acc[mt][nh][2] + b0; v1.y = acc[mt][nh][3] + b1;
            if (RESID) {
                float2 rs0 = *(const float2*)&resid[(size_t)r0 * N + cc];
                float2 rs1 = *(const float2*)&resid[(size_t)r1 * N + cc];
                v0.x += rs0.x; v0.y += rs0.y;
                v1.x += rs1.x; v1.y += rs1.y;
            }
            *(float2*)&C[(size_t)r0 * N + cc] = v0;
            *(float2*)&C[(size_t)r1 * N + cc] = v1;
        }
    }
}

// ---------------------------------------------------------------------------
// Kernel 3: RoPE in place on q (heads 0..31) and k (heads 32..39)
// ---------------------------------------------------------------------------
__global__ void rope_kernel(const float* __restrict__ cosT,
                            const float* __restrict__ sinT) {
    int idx = blockIdx.x * blockDim.x + threadIdx.x;
    if (idx >= T_SEQ * 40 * 32) return;
    int d = idx & 31;
    int rest = idx >> 5;
    int head = rest % 40;
    int t = rest / 40;
    float c = cosT[t * 32 + d];
    float s = sinT[t * 32 + d];
    float* p = g_qkv + (size_t)t * QKVD + head * 64 + d;
    float x1 = p[0];
    float x2 = p[32];
    p[0] = x1 * c - x2 * s;
    p[32] = x2 * c + x1 * s;
}

// ---------------------------------------------------------------------------
// Kernel 4: sliding-window GQA attention with sinks
// ---------------------------------------------------------------------------
#define TQ 16
#define SM_Q 0
#define SM_K (64 * 65)
#define SM_V (SM_K + 144 * 65)
#define SM_S (SM_V + 144 * 68)
#define SM_TOTAL (SM_S + 64 * 145)

__global__ void attn_kernel(const float* __restrict__ sinks) {
    extern __shared__ float sm[];
    float* Qs = sm + SM_Q;   // [64][65]  row = m*16+qi
    float* Ks = sm + SM_K;   // [144][65]
    float* Vs = sm + SM_V;   // [144][68]
    float* Ss = sm + SM_S;   // [64][145]

    int qb = blockIdx.x;
    int n = blockIdx.y;
    int qstart = qb * TQ;
    int kmin = qstart - SW; if (kmin < 0) kmin = 0;
    int nkey = qstart + TQ - kmin;   // <= 144
    int tid = threadIdx.x;

    for (int v = tid; v < 64 * 16; v += 256) {
        int row = v >> 4;
        int d4 = (v & 15) * 4;
        int m = row >> 4, qi = row & 15;
        float4 q = *(const float4*)&g_qkv[(size_t)(qstart + qi) * QKVD + n * 256 + m * 64 + d4];
        Qs[row * 65 + d4 + 0] = q.x;
        Qs[row * 65 + d4 + 1] = q.y;
        Qs[row * 65 + d4 + 2] = q.z;
        Qs[row * 65 + d4 + 3] = q.w;
    }
    for (int v = tid; v < nkey * 16; v += 256) {
        int r = v >> 4;
        int d4 = (v & 15) * 4;
        int kg = kmin + r;
        float4 kk = *(const float4*)&g_qkv[(size_t)kg * QKVD + 2048 + n * 64 + d4];
        Ks[r * 65 + d4 + 0] = kk.x;
        Ks[r * 65 + d4 + 1] = kk.y;
        Ks[r * 65 + d4 + 2] = kk.z;
        Ks[r * 65 + d4 + 3] = kk.w;
        float4 vv = *(const float4*)&g_qkv[(size_t)kg * QKVD + 2560 + n * 64 + d4];
        *(float4*)&Vs[r * 68 + d4] = vv;
    }
    __syncthreads();

    int tx = tid & 15, ty = tid >> 4;
    int r0 = ty * 4;
    int k0 = tx * 9;

    float acc[4][9];
#pragma unroll
    for (int i = 0; i < 4; i++)
#pragma unroll
        for (int j = 0; j < 9; j++) acc[i][j] = 0.0f;
#pragma unroll 8
    for (int d = 0; d < 64; d++) {
        float qa[4], kb[9];
#pragma unroll
        for (int i = 0; i < 4; i++) qa[i] = Qs[(r0 + i) * 65 + d];
#pragma unroll
        for (int j = 0; j < 9; j++) kb[j] = Ks[(k0 + j) * 65 + d];
#pragma unroll
        for (int i = 0; i < 4; i++)
#pragma unroll
            for (int j = 0; j < 9; j++) acc[i][j] = fmaf(qa[i], kb[j], acc[i][j]);
    }
#pragma unroll
    for (int j = 0; j < 9; j++) {
        int key = k0 + j;
        if (key < nkey) {
            int kg = kmin + key;
#pragma unroll
            for (int i = 0; i < 4; i++) {
                int row = r0 + i;
                int qg = qstart + (row & 15);
                float s;
                if (kg <= qg && (qg - kg) <= SW) s = acc[i][j] * 0.125f;
                else s = -1e30f;
                Ss[row * 145 + key] = s;
            }
        }
    }
    __syncthreads();

    int wid = tid >> 5, lane = tid & 31;
    for (int rr = 0; rr < 8; rr++) {
        int row = wid * 8 + rr;
        int m = row >> 4;
        float s0 = sinks[n * QM + m];
        float vmax = -1e30f;
        for (int k = lane; k < nkey; k += 32) vmax = fmaxf(vmax, Ss[row * 145 + k]);
#pragma unroll
        for (int off = 16; off > 0; off >>= 1)
            vmax = fmaxf(vmax, __shfl_xor_sync(0xffffffffu, vmax, off));
        vmax = fmaxf(vmax, s0);
        float vsum = 0.0f;
        for (int k = lane; k < nkey; k += 32) {
            float e = __expf(Ss[row * 145 + k] - vmax);
            Ss[row * 145 + k] = e;
            vsum += e;
        }
#pragma unroll
        for (int off = 16; off > 0; off >>= 1)
            vsum += __shfl_xor_sync(0xffffffffu, vsum, off);
        vsum += __expf(s0 - vmax);
        float inv = 1.0f / vsum;
        for (int k = lane; k < nkey; k += 32) Ss[row * 145 + k] *= inv;
    }
    __syncthreads();

    int c0 = tx * 4;
    float o[4][4];
#pragma unroll
    for (int i = 0; i < 4; i++)
#pragma unroll
        for (int j = 0; j < 4; j++) o[i][j] = 0.0f;
    for (int k = 0; k < nkey; k++) {
        float4 vv = *(float4*)&Vs[k * 68 + c0];
        float ws[4];
#pragma unroll
        for (int i = 0; i < 4; i++) ws[i] = Ss[(r0 + i) * 145 + k];
#pragma unroll
        for (int i = 0; i < 4; i++) {
            o[i][0] = fmaf(ws[i], vv.x, o[i][0]);
            o[i][1] = fmaf(ws[i], vv.y, o[i][1]);
            o[i][2] = fmaf(ws[i], vv.z, o[i][2]);
            o[i][3] = fmaf(ws[i], vv.w, o[i][3]);
        }
    }
#pragma unroll
    for (int i = 0; i < 4; i++) {
        int row = r0 + i;
        int t = qstart + (row & 15);
        int m = row >> 4;
        int col = n * 256 + m * 64 + c0;
        float4 r;
        r.x = o[i][0]; r.y = o[i][1]; r.z = o[i][2]; r.w = o[i][3];
        *(float4*)&g_attn[(size_t)t * H_DIM + col] = r;
    }
}

// ---------------------------------------------------------------------------
// Launch
// ---------------------------------------------------------------------------
extern "C" void kernel_launch(void* const* d_in, const int* in_sizes, int n_in,
                              void* d_out, int out_size) {
    const float* x       = (const float*)d_in[0];
    const float* scale   = (const float*)d_in[1];
    const float* sinks   = (const float*)d_in[2];
    const float* qkvW    = (const float*)d_in[3];
    const float* qkvB    = (const float*)d_in[4];
    const float* outW    = (const float*)d_in[5];
    const float* outB    = (const float*)d_in[6];
    const float* cosT    = (const float*)d_in[7];
    const float* sinT    = (const float*)d_in[8];
    float* out = (float*)d_out;

    float *p_normed, *p_qkv, *p_attn;
    cudaGetSymbolAddress((void**)&p_normed, g_normed);
    cudaGetSymbolAddress((void**)&p_qkv, g_qkv);
    cudaGetSymbolAddress((void**)&p_attn, g_attn);

    // 1. RMSNorm
    rmsnorm_kernel<<<T_SEQ, 256>>>(x, scale, p_normed);

    // 2. QKV GEMM (tensor cores, 3xBF16): [2048,2048] @ [2048,3072] + bias
    {
        dim3 grid(QKVD / 128, T_SEQ / 128);
        gemm_mma<false><<<grid, 256>>>(p_normed, qkvW, qkvB, nullptr, p_qkv,
                                       T_SEQ, QKVD, H_DIM);
    }

    // 3. RoPE on q + k
    {
        int total = T_SEQ * 40 * 32;
        rope_kernel<<<(total + 255) / 256, 256>>>(cosT, sinT);
    }

    // 4. Attention
    {
        cudaFuncSetAttribute(attn_kernel, cudaFuncAttributeMaxDynamicSharedMemorySize,
                             SM_TOTAL * (int)sizeof(float));
        dim3 grid(T_SEQ / TQ, NKV);
        attn_kernel<<<grid, 256, SM_TOTAL * sizeof(float)>>>(sinks);
    }

    // 5. Output projection + residual (tensor cores, 3xBF16)
    {
        dim3 grid(H_DIM / 128, T_SEQ / 128);
        gemm_mma<true><<<grid, 256>>>(p_attn, outW, outB, x, out,
                                      T_SEQ, H_DIM, H_DIM);
    }
}

// round 5
// speedup vs baseline: 2.0771x; 1.0933x over previous
#include <cuda_runtime.h>
#include <cuda_bf16.h>
#include <math.h>

// Problem constants
#define T_SEQ 2048
#define H_DIM 2048
#define NH 32
#define NKV 8
#define HD 64
#define SW 128
#define QM 4              // NH / NKV
#define QKVD 3072         // HD*(NH+2*NKV)
#define EPS 1e-5f

typedef unsigned short ushort_t;

// Scratch (device globals; no allocation allowed)
__device__ float g_qkv[T_SEQ * QKVD];
__device__ ushort_t g_nhi[T_SEQ * H_DIM];      // rmsnorm out, hi bf16
__device__ ushort_t g_nlo[T_SEQ * H_DIM];      // rmsnorm out, lo bf16
__device__ ushort_t g_ahi[T_SEQ * H_DIM];      // attn out, hi bf16
__device__ ushort_t g_alo[T_SEQ * H_DIM];      // attn out, lo bf16
__device__ ushort_t g_wqkv_hi[QKVD * H_DIM];   // qkv weight, [N][K] bf16 hi
__device__ ushort_t g_wqkv_lo[QKVD * H_DIM];
__device__ ushort_t g_wout_hi[H_DIM * H_DIM];  // out weight, [N][K] bf16 hi
__device__ ushort_t g_wout_lo[H_DIM * H_DIM];

__device__ __forceinline__ ushort_t bf_bits(float x) {
    __nv_bfloat16 h = __float2bfloat16(x);
    return *reinterpret_cast<ushort_t*>(&h);
}
__device__ __forceinline__ float bf_val(ushort_t u) {
    __nv_bfloat16 h = *reinterpret_cast<__nv_bfloat16*>(&u);
    return __bfloat162float(h);
}

// ---------------------------------------------------------------------------
// Kernel 0: weight split + transpose.  W[K][N] fp32 -> Whi/Wlo[N][K] bf16
// ---------------------------------------------------------------------------
__global__ void split_transpose(const float* __restrict__ W,
                                ushort_t* __restrict__ Whi,
                                ushort_t* __restrict__ Wlo, int K, int N) {
    __shared__ float t[32][33];
    int n0 = blockIdx.x * 32, k0 = blockIdx.y * 32;
    int tx = threadIdx.x, ty = threadIdx.y;  // 32 x 8
#pragma unroll
    for (int i = 0; i < 4; i++)
        t[ty + i * 8][tx] = W[(size_t)(k0 + ty + i * 8) * N + n0 + tx];
    __syncthreads();
#pragma unroll
    for (int i = 0; i < 4; i++) {
        int n = ty + i * 8;
        float x = t[tx][n];
        ushort_t h = bf_bits(x);
        ushort_t l = bf_bits(x - bf_val(h));
        Whi[(size_t)(n0 + n) * K + k0 + tx] = h;
        Wlo[(size_t)(n0 + n) * K + k0 + tx] = l;
    }
}

// ---------------------------------------------------------------------------
// Kernel 1: RMSNorm per row, emits bf16 hi/lo directly
// ---------------------------------------------------------------------------
__global__ void rmsnorm_kernel(const float* __restrict__ x,
                               const float* __restrict__ scale,
                               ushort_t* __restrict__ ohi,
                               ushort_t* __restrict__ olo) {
    __shared__ float red[256];
    int row = blockIdx.x;
    int tid = threadIdx.x;
    const float4* xr = (const float4*)(x + (size_t)row * H_DIM);
    float4 v0 = xr[tid];
    float4 v1 = xr[tid + 256];
    float ss = v0.x * v0.x + v0.y * v0.y + v0.z * v0.z + v0.w * v0.w
             + v1.x * v1.x + v1.y * v1.y + v1.z * v1.z + v1.w * v1.w;
    red[tid] = ss;
    __syncthreads();
    for (int s = 128; s > 0; s >>= 1) {
        if (tid < s) red[tid] += red[tid + s];
        __syncthreads();
    }
    float inv = rsqrtf(red[0] * (1.0f / H_DIM) + EPS);
    const float4* sc = (const float4*)scale;
    float4 s0 = sc[tid], s1 = sc[tid + 256];
    float o[8];
    o[0] = v0.x * inv * s0.x; o[1] = v0.y * inv * s0.y;
    o[2] = v0.z * inv * s0.z; o[3] = v0.w * inv * s0.w;
    o[4] = v1.x * inv * s1.x; o[5] = v1.y * inv * s1.y;
    o[6] = v1.z * inv * s1.z; o[7] = v1.w * inv * s1.w;
    ushort_t h[8], l[8];
#pragma unroll
    for (int i = 0; i < 8; i++) {
        h[i] = bf_bits(o[i]);
        l[i] = bf_bits(o[i] - bf_val(h[i]));
    }
    size_t base = (size_t)row * H_DIM;
    uint2 h0 = make_uint2((unsigned)h[0] | ((unsigned)h[1] << 16),
                          (unsigned)h[2] | ((unsigned)h[3] << 16));
    uint2 h1 = make_uint2((unsigned)h[4] | ((unsigned)h[5] << 16),
                          (unsigned)h[6] | ((unsigned)h[7] << 16));
    uint2 l0 = make_uint2((unsigned)l[0] | ((unsigned)l[1] << 16),
                          (unsigned)l[2] | ((unsigned)l[3] << 16));
    uint2 l1 = make_uint2((unsigned)l[4] | ((unsigned)l[5] << 16),
                          (unsigned)l[6] | ((unsigned)l[7] << 16));
    *(uint2*)&ohi[base + tid * 4] = h0;
    *(uint2*)&ohi[base + 1024 + tid * 4] = h1;
    *(uint2*)&olo[base + tid * 4] = l0;
    *(uint2*)&olo[base + 1024 + tid * 4] = l1;
}

// ---------------------------------------------------------------------------
// Tensor-core GEMM, 3xBF16 split, pre-split operands, K-major B, cp.async
// double buffering.  C = A@B^T(view) + bias (+resid)
// A: [M][K] bf16 hi/lo,  B: [N][K] bf16 hi/lo,  C: [M][N] fp32
// BM=BN=128, BK=32, 256 threads (8 warps, 4x2)
// ---------------------------------------------------------------------------
#define PAD 40
#define ARR_ELEMS (128 * PAD)            // 5120 bf16 per array
#define STAGE_ELEMS (4 * ARR_ELEMS)      // AsHi, AsLo, BsHi, BsLo
#define GEMM_SMEM_BYTES (2 * STAGE_ELEMS * 2)

#define CP16(dst_u32, src_ptr) \
    asm volatile("cp.async.cg.shared.global [%0], [%1], 16;\n" \
                 :: "r"(dst_u32), "l"(src_ptr))

__device__ __forceinline__ void mma16816(float* c, const unsigned* a, const unsigned* b) {
    asm volatile(
        "mma.sync.aligned.m16n8k16.row.col.f32.bf16.bf16.f32 "
        "{%0,%1,%2,%3}, {%4,%5,%6,%7}, {%8,%9}, {%0,%1,%2,%3};\n"
        : "+f"(c[0]), "+f"(c[1]), "+f"(c[2]), "+f"(c[3])
        : "r"(a[0]), "r"(a[1]), "r"(a[2]), "r"(a[3]), "r"(b[0]), "r"(b[1]));
}

template <bool RESID>
__global__ __launch_bounds__(256, 2)
void gemm_mma(const ushort_t* __restrict__ Ahi, const ushort_t* __restrict__ Alo,
              const ushort_t* __restrict__ Bhi, const ushort_t* __restrict__ Blo,
              const float* __restrict__ bias, const float* __restrict__ resid,
              float* __restrict__ C, int M, int N, int K) {
    extern __shared__ ushort_t smem[];
    unsigned smem_u32;
    {
        void* p = smem;
        smem_u32 = (unsigned)__cvta_generic_to_shared(p);
    }

    int tid = threadIdx.x;
    int lane = tid & 31;
    int wid = tid >> 5;
    int warp_m = wid & 3;
    int warp_n = wid >> 2;
    int row0 = blockIdx.y * 128;
    int col0 = blockIdx.x * 128;

    float acc[2][8][4];
#pragma unroll
    for (int i = 0; i < 2; i++)
#pragma unroll
        for (int j = 0; j < 8; j++)
#pragma unroll
            for (int l = 0; l < 4; l++) acc[i][j][l] = 0.0f;

    int r_ld = tid >> 2;          // 0..63 (plus +64 on second pass)
    int c_ld = tid & 3;           // 16B chunk within 32-k row

    auto load_stage = [&](int buf, int k0) {
        unsigned sbase = smem_u32 + buf * (STAGE_ELEMS * 2);
#pragma unroll
        for (int i = 0; i < 2; i++) {
            int r = r_ld + i * 64;
            unsigned soff = (unsigned)((r * PAD + c_ld * 8) * 2);
            size_t ga = (size_t)(row0 + r) * K + k0 + c_ld * 8;
            size_t gb = (size_t)(col0 + r) * K + k0 + c_ld * 8;
            CP16(sbase + soff, Ahi + ga);
            CP16(sbase + ARR_ELEMS * 2 + soff, Alo + ga);
            CP16(sbase + 2 * ARR_ELEMS * 2 + soff, Bhi + gb);
            CP16(sbase + 3 * ARR_ELEMS * 2 + soff, Blo + gb);
        }
    };

    int T = K / 32;
    load_stage(0, 0);
    asm volatile("cp.async.commit_group;\n");

    for (int t = 0; t < T; t++) {
        if (t + 1 < T) {
            load_stage((t + 1) & 1, (t + 1) * 32);
            asm volatile("cp.async.commit_group;\n");
            asm volatile("cp.async.wait_group 1;\n");
        } else {
            asm volatile("cp.async.wait_group 0;\n");
        }
        __syncthreads();

        const ushort_t* AsHi = smem + (t & 1) * STAGE_ELEMS;
        const ushort_t* AsLo = AsHi + ARR_ELEMS;
        const ushort_t* BsHi = AsLo + ARR_ELEMS;
        const ushort_t* BsLo = BsHi + ARR_ELEMS;

#pragma unroll
        for (int ks = 0; ks < 32; ks += 16) {
            int kk = ks + (lane & 3) * 2;
            unsigned ah[2][4], al[2][4];
#pragma unroll
            for (int mt = 0; mt < 2; mt++) {
                int row = warp_m * 32 + mt * 16 + (lane >> 2);
                ah[mt][0] = *(const unsigned*)&AsHi[row * PAD + kk];
                ah[mt][1] = *(const unsigned*)&AsHi[(row + 8) * PAD + kk];
                ah[mt][2] = *(const unsigned*)&AsHi[row * PAD + kk + 8];
                ah[mt][3] = *(const unsigned*)&AsHi[(row + 8) * PAD + kk + 8];
                al[mt][0] = *(const unsigned*)&AsLo[row * PAD + kk];
                al[mt][1] = *(const unsigned*)&AsLo[(row + 8) * PAD + kk];
                al[mt][2] = *(const unsigned*)&AsLo[row * PAD + kk + 8];
                al[mt][3] = *(const unsigned*)&AsLo[(row + 8) * PAD + kk + 8];
            }
#pragma unroll
            for (int nh = 0; nh < 8; nh++) {
                int n = warp_n * 64 + nh * 8 + (lane >> 2);
                unsigned bh[2], bl[2];
                bh[0] = *(const unsigned*)&BsHi[n * PAD + kk];
                bh[1] = *(const unsigned*)&BsHi[n * PAD + kk + 8];
                bl[0] = *(const unsigned*)&BsLo[n * PAD + kk];
                bl[1] = *(const unsigned*)&BsLo[n * PAD + kk + 8];
#pragma unroll
                for (int mt = 0; mt < 2; mt++) {
                    mma16816(acc[mt][nh], ah[mt], bh);
                    mma16816(acc[mt][nh], ah[mt], bl);
                    mma16816(acc[mt][nh], al[mt], bh);
                }
            }
        }
        __syncthreads();
    }

    // ---- epilogue: bias (+resid) ----
#pragma unroll
    for (int mt = 0; mt < 2; mt++) {
        int r0 = row0 + warp_m * 32 + mt * 16 + (lane >> 2);
        int r1 = r0 + 8;
#pragma unroll
        for (int nh = 0; nh < 8; nh++) {
            int cc = col0 + warp_n * 64 + nh * 8 + (lane & 3) * 2;
            float b0 = bias[cc], b1 = bias[cc + 1];
            float2 v0, v1;
            v0.x = acc[mt][nh][0] + b0; v0.y = acc[mt][nh][1] + b1;
            v1.x = acc[mt][nh][2] + b0; v1.y = acc[mt][nh][3] + b1;
            if (RESID) {
                float2 rs0 = *(const float2*)&resid[(size_t)r0 * N + cc];
                float2 rs1 = *(const float2*)&resid[(size_t)r1 * N + cc];
                v0.x += rs0.x; v0.y += rs0.y;
                v1.x += rs1.x; v1.y += rs1.y;
            }
            *(float2*)&C[(size_t)r0 * N + cc] = v0;
            *(float2*)&C[(size_t)r1 * N + cc] = v1;
        }
    }
}

// ---------------------------------------------------------------------------
// Kernel 3: RoPE in place on q (heads 0..31) and k (heads 32..39)
// ---------------------------------------------------------------------------
__global__ void rope_kernel(const float* __restrict__ cosT,
                            const float* __restrict__ sinT) {
    int idx = blockIdx.x * blockDim.x + threadIdx.x;
    if (idx >= T_SEQ * 40 * 32) return;
    int d = idx & 31;
    int rest = idx >> 5;
    int head = rest % 40;
    int t = rest / 40;
    float c = cosT[t * 32 + d];
    float s = sinT[t * 32 + d];
    float* p = g_qkv + (size_t)t * QKVD + head * 64 + d;
    float x1 = p[0];
    float x2 = p[32];
    p[0] = x1 * c - x2 * s;
    p[32] = x2 * c + x1 * s;
}

// ---------------------------------------------------------------------------
// Kernel 4: sliding-window GQA attention with sinks; emits bf16 hi/lo
// ---------------------------------------------------------------------------
#define TQ 16
#define SM_Q 0
#define SM_K (64 * 65)
#define SM_V (SM_K + 144 * 65)
#define SM_S (SM_V + 144 * 68)
#define SM_TOTAL (SM_S + 64 * 145)

__global__ void attn_kernel(const float* __restrict__ sinks) {
    extern __shared__ float sm[];
    float* Qs = sm + SM_Q;
    float* Ks = sm + SM_K;
    float* Vs = sm + SM_V;
    float* Ss = sm + SM_S;

    int qb = blockIdx.x;
    int n = blockIdx.y;
    int qstart = qb * TQ;
    int kmin = qstart - SW; if (kmin < 0) kmin = 0;
    int nkey = qstart + TQ - kmin;
    int tid = threadIdx.x;

    for (int v = tid; v < 64 * 16; v += 256) {
        int row = v >> 4;
        int d4 = (v & 15) * 4;
        int m = row >> 4, qi = row & 15;
        float4 q = *(const float4*)&g_qkv[(size_t)(qstart + qi) * QKVD + n * 256 + m * 64 + d4];
        Qs[row * 65 + d4 + 0] = q.x;
        Qs[row * 65 + d4 + 1] = q.y;
        Qs[row * 65 + d4 + 2] = q.z;
        Qs[row * 65 + d4 + 3] = q.w;
    }
    for (int v = tid; v < nkey * 16; v += 256) {
        int r = v >> 4;
        int d4 = (v & 15) * 4;
        int kg = kmin + r;
        float4 kk = *(const float4*)&g_qkv[(size_t)kg * QKVD + 2048 + n * 64 + d4];
        Ks[r * 65 + d4 + 0] = kk.x;
        Ks[r * 65 + d4 + 1] = kk.y;
        Ks[r * 65 + d4 + 2] = kk.z;
        Ks[r * 65 + d4 + 3] = kk.w;
        float4 vv = *(const float4*)&g_qkv[(size_t)kg * QKVD + 2560 + n * 64 + d4];
        *(float4*)&Vs[r * 68 + d4] = vv;
    }
    __syncthreads();

    int tx = tid & 15, ty = tid >> 4;
    int r0 = ty * 4;
    int k0 = tx * 9;

    float acc[4][9];
#pragma unroll
    for (int i = 0; i < 4; i++)
#pragma unroll
        for (int j = 0; j < 9; j++) acc[i][j] = 0.0f;
#pragma unroll 8
    for (int d = 0; d < 64; d++) {
        float qa[4], kb[9];
#pragma unroll
        for (int i = 0; i < 4; i++) qa[i] = Qs[(r0 + i) * 65 + d];
#pragma unroll
        for (int j = 0; j < 9; j++) kb[j] = Ks[(k0 + j) * 65 + d];
#pragma unroll
        for (int i = 0; i < 4; i++)
#pragma unroll
            for (int j = 0; j < 9; j++) acc[i][j] = fmaf(qa[i], kb[j], acc[i][j]);
    }
#pragma unroll
    for (int j = 0; j < 9; j++) {
        int key = k0 + j;
        if (key < nkey) {
            int kg = kmin + key;
#pragma unroll
            for (int i = 0; i < 4; i++) {
                int row = r0 + i;
                int qg = qstart + (row & 15);
                float s;
                if (kg <= qg && (qg - kg) <= SW) s = acc[i][j] * 0.125f;
                else s = -1e30f;
                Ss[row * 145 + key] = s;
            }
        }
    }
    __syncthreads();

    int wid = tid >> 5, lane = tid & 31;
    for (int rr = 0; rr < 8; rr++) {
        int row = wid * 8 + rr;
        int m = row >> 4;
        float s0 = sinks[n * QM + m];
        float vmax = -1e30f;
        for (int k = lane; k < nkey; k += 32) vmax = fmaxf(vmax, Ss[row * 145 + k]);
#pragma unroll
        for (int off = 16; off > 0; off >>= 1)
            vmax = fmaxf(vmax, __shfl_xor_sync(0xffffffffu, vmax, off));
        vmax = fmaxf(vmax, s0);
        float vsum = 0.0f;
        for (int k = lane; k < nkey; k += 32) {
            float e = __expf(Ss[row * 145 + k] - vmax);
            Ss[row * 145 + k] = e;
            vsum += e;
        }
#pragma unroll
        for (int off = 16; off > 0; off >>= 1)
            vsum += __shfl_xor_sync(0xffffffffu, vsum, off);
        vsum += __expf(s0 - vmax);
        float inv = 1.0f / vsum;
        for (int k = lane; k < nkey; k += 32) Ss[row * 145 + k] *= inv;
    }
    __syncthreads();

    int c0 = tx * 4;
    float o[4][4];
#pragma unroll
    for (int i = 0; i < 4; i++)
#pragma unroll
        for (int j = 0; j < 4; j++) o[i][j] = 0.0f;
    for (int k = 0; k < nkey; k++) {
        float4 vv = *(float4*)&Vs[k * 68 + c0];
        float ws[4];
#pragma unroll
        for (int i = 0; i < 4; i++) ws[i] = Ss[(r0 + i) * 145 + k];
#pragma unroll
        for (int i = 0; i < 4; i++) {
            o[i][0] = fmaf(ws[i], vv.x, o[i][0]);
            o[i][1] = fmaf(ws[i], vv.y, o[i][1]);
            o[i][2] = fmaf(ws[i], vv.z, o[i][2]);
            o[i][3] = fmaf(ws[i], vv.w, o[i][3]);
        }
    }
#pragma unroll
    for (int i = 0; i < 4; i++) {
        int row = r0 + i;
        int t = qstart + (row & 15);
        int m = row >> 4;
        size_t col = (size_t)t * H_DIM + n * 256 + m * 64 + c0;
        ushort_t h[4], l[4];
#pragma unroll
        for (int j = 0; j < 4; j++) {
            h[j] = bf_bits(o[i][j]);
            l[j] = bf_bits(o[i][j] - bf_val(h[j]));
        }
        *(uint2*)&g_ahi[col] = make_uint2((unsigned)h[0] | ((unsigned)h[1] << 16),
                                          (unsigned)h[2] | ((unsigned)h[3] << 16));
        *(uint2*)&g_alo[col] = make_uint2((unsigned)l[0] | ((unsigned)l[1] << 16),
                                          (unsigned)l[2] | ((unsigned)l[3] << 16));
    }
}

// ---------------------------------------------------------------------------
// Launch
// ---------------------------------------------------------------------------
extern "C" void kernel_launch(void* const* d_in, const int* in_sizes, int n_in,
                              void* d_out, int out_size) {
    const float* x       = (const float*)d_in[0];
    const float* scale   = (const float*)d_in[1];
    const float* sinks   = (const float*)d_in[2];
    const float* qkvW    = (const float*)d_in[3];
    const float* qkvB    = (const float*)d_in[4];
    const float* outW    = (const float*)d_in[5];
    const float* outB    = (const float*)d_in[6];
    const float* cosT    = (const float*)d_in[7];
    const float* sinT    = (const float*)d_in[8];
    float* out = (float*)d_out;

    ushort_t *p_nhi, *p_nlo, *p_ahi, *p_alo;
    ushort_t *p_wqkv_hi, *p_wqkv_lo, *p_wout_hi, *p_wout_lo;
    cudaGetSymbolAddress((void**)&p_nhi, g_nhi);
    cudaGetSymbolAddress((void**)&p_nlo, g_nlo);
    cudaGetSymbolAddress((void**)&p_ahi, g_ahi);
    cudaGetSymbolAddress((void**)&p_alo, g_alo);
    cudaGetSymbolAddress((void**)&p_wqkv_hi, g_wqkv_hi);
    cudaGetSymbolAddress((void**)&p_wqkv_lo, g_wqkv_lo);
    cudaGetSymbolAddress((void**)&p_wout_hi, g_wout_hi);
    cudaGetSymbolAddress((void**)&p_wout_lo, g_wout_lo);
    float* p_qkv;
    cudaGetSymbolAddress((void**)&p_qkv, g_qkv);

    // 0. split+transpose weights
    {
        dim3 blk(32, 8);
        split_transpose<<<dim3(QKVD / 32, H_DIM / 32), blk>>>(qkvW, p_wqkv_hi, p_wqkv_lo,
                                                              H_DIM, QKVD);
        split_transpose<<<dim3(H_DIM / 32, H_DIM / 32), blk>>>(outW, p_wout_hi, p_wout_lo,
                                                               H_DIM, H_DIM);
    }

    // 1. RMSNorm -> bf16 hi/lo
    rmsnorm_kernel<<<T_SEQ, 256>>>(x, scale, p_nhi, p_nlo);

    // 2. QKV GEMM
    {
        cudaFuncSetAttribute(gemm_mma<false>, cudaFuncAttributeMaxDynamicSharedMemorySize,
                             GEMM_SMEM_BYTES);
        dim3 grid(QKVD / 128, T_SEQ / 128);
        gemm_mma<false><<<grid, 256, GEMM_SMEM_BYTES>>>(p_nhi, p_nlo, p_wqkv_hi, p_wqkv_lo,
                                                        qkvB, nullptr, p_qkv,
                                                        T_SEQ, QKVD, H_DIM);
    }

    // 3. RoPE on q + k
    {
        int total = T_SEQ * 40 * 32;
        rope_kernel<<<(total + 255) / 256, 256>>>(cosT, sinT);
    }

    // 4. Attention -> bf16 hi/lo
    {
        cudaFuncSetAttribute(attn_kernel, cudaFuncAttributeMaxDynamicSharedMemorySize,
                             SM_TOTAL * (int)sizeof(float));
        dim3 grid(T_SEQ / TQ, NKV);
        attn_kernel<<<grid, 256, SM_TOTAL * sizeof(float)>>>(sinks);
    }

    // 5. Output projection + residual
    {
        cudaFuncSetAttribute(gemm_mma<true>, cudaFuncAttributeMaxDynamicSharedMemorySize,
                             GEMM_SMEM_BYTES);
        dim3 grid(H_DIM / 128, T_SEQ / 128);
        gemm_mma<true><<<grid, 256, GEMM_SMEM_BYTES>>>(p_ahi, p_alo, p_wout_hi, p_wout_lo,
                                                       outB, x, out,
                                                       T_SEQ, H_DIM, H_DIM);
    }
}

// round 6
// speedup vs baseline: 2.1162x; 1.0189x over previous
#include <cuda_runtime.h>
#include <cuda_bf16.h>
#include <math.h>

// Problem constants
#define T_SEQ 2048
#define H_DIM 2048
#define NH 32
#define NKV 8
#define HD 64
#define SW 128
#define QM 4              // NH / NKV
#define QKVD 3072         // HD*(NH+2*NKV)
#define EPS 1e-5f

typedef unsigned short ushort_t;

// Scratch (device globals; no allocation allowed)
__device__ float g_qkv[T_SEQ * QKVD];
__device__ ushort_t g_nhi[T_SEQ * H_DIM];      // rmsnorm out, hi bf16
__device__ ushort_t g_nlo[T_SEQ * H_DIM];      // rmsnorm out, lo bf16
__device__ ushort_t g_ahi[T_SEQ * H_DIM];      // attn out, hi bf16
__device__ ushort_t g_alo[T_SEQ * H_DIM];      // attn out, lo bf16
__device__ ushort_t g_wqkv_hi[QKVD * H_DIM];   // qkv weight, [N][K] bf16 hi
__device__ ushort_t g_wqkv_lo[QKVD * H_DIM];
__device__ ushort_t g_wout_hi[H_DIM * H_DIM];  // out weight, [N][K] bf16 hi
__device__ ushort_t g_wout_lo[H_DIM * H_DIM];

__device__ __forceinline__ ushort_t bf_bits(float x) {
    __nv_bfloat16 h = __float2bfloat16(x);
    return *reinterpret_cast<ushort_t*>(&h);
}
__device__ __forceinline__ float bf_val(ushort_t u) {
    __nv_bfloat16 h = *reinterpret_cast<__nv_bfloat16*>(&u);
    return __bfloat162float(h);
}

// ---------------------------------------------------------------------------
// Kernel 0: weight split + transpose.  W[K][N] fp32 -> Whi/Wlo[N][K] bf16
// ---------------------------------------------------------------------------
__global__ void split_transpose(const float* __restrict__ W,
                                ushort_t* __restrict__ Whi,
                                ushort_t* __restrict__ Wlo, int K, int N) {
    __shared__ float t[32][33];
    int n0 = blockIdx.x * 32, k0 = blockIdx.y * 32;
    int tx = threadIdx.x, ty = threadIdx.y;  // 32 x 8
#pragma unroll
    for (int i = 0; i < 4; i++)
        t[ty + i * 8][tx] = W[(size_t)(k0 + ty + i * 8) * N + n0 + tx];
    __syncthreads();
#pragma unroll
    for (int i = 0; i < 4; i++) {
        int n = ty + i * 8;
        float x = t[tx][n];
        ushort_t h = bf_bits(x);
        ushort_t l = bf_bits(x - bf_val(h));
        Whi[(size_t)(n0 + n) * K + k0 + tx] = h;
        Wlo[(size_t)(n0 + n) * K + k0 + tx] = l;
    }
}

// ---------------------------------------------------------------------------
// Kernel 1: RMSNorm per row, emits bf16 hi/lo directly
// ---------------------------------------------------------------------------
__global__ void rmsnorm_kernel(const float* __restrict__ x,
                               const float* __restrict__ scale,
                               ushort_t* __restrict__ ohi,
                               ushort_t* __restrict__ olo) {
    __shared__ float red[256];
    int row = blockIdx.x;
    int tid = threadIdx.x;
    const float4* xr = (const float4*)(x + (size_t)row * H_DIM);
    float4 v0 = xr[tid];
    float4 v1 = xr[tid + 256];
    float ss = v0.x * v0.x + v0.y * v0.y + v0.z * v0.z + v0.w * v0.w
             + v1.x * v1.x + v1.y * v1.y + v1.z * v1.z + v1.w * v1.w;
    red[tid] = ss;
    __syncthreads();
    for (int s = 128; s > 0; s >>= 1) {
        if (tid < s) red[tid] += red[tid + s];
        __syncthreads();
    }
    float inv = rsqrtf(red[0] * (1.0f / H_DIM) + EPS);
    const float4* sc = (const float4*)scale;
    float4 s0 = sc[tid], s1 = sc[tid + 256];
    float o[8];
    o[0] = v0.x * inv * s0.x; o[1] = v0.y * inv * s0.y;
    o[2] = v0.z * inv * s0.z; o[3] = v0.w * inv * s0.w;
    o[4] = v1.x * inv * s1.x; o[5] = v1.y * inv * s1.y;
    o[6] = v1.z * inv * s1.z; o[7] = v1.w * inv * s1.w;
    ushort_t h[8], l[8];
#pragma unroll
    for (int i = 0; i < 8; i++) {
        h[i] = bf_bits(o[i]);
        l[i] = bf_bits(o[i] - bf_val(h[i]));
    }
    size_t base = (size_t)row * H_DIM;
    uint2 h0 = make_uint2((unsigned)h[0] | ((unsigned)h[1] << 16),
                          (unsigned)h[2] | ((unsigned)h[3] << 16));
    uint2 h1 = make_uint2((unsigned)h[4] | ((unsigned)h[5] << 16),
                          (unsigned)h[6] | ((unsigned)h[7] << 16));
    uint2 l0 = make_uint2((unsigned)l[0] | ((unsigned)l[1] << 16),
                          (unsigned)l[2] | ((unsigned)l[3] << 16));
    uint2 l1 = make_uint2((unsigned)l[4] | ((unsigned)l[5] << 16),
                          (unsigned)l[6] | ((unsigned)l[7] << 16));
    *(uint2*)&ohi[base + tid * 4] = h0;
    *(uint2*)&ohi[base + 1024 + tid * 4] = h1;
    *(uint2*)&olo[base + tid * 4] = l0;
    *(uint2*)&olo[base + 1024 + tid * 4] = l1;
}

// ---------------------------------------------------------------------------
// Tensor-core GEMM, 3xBF16 split, pre-split operands, K-major B, cp.async
// double buffering, ldmatrix fragment loads.
// A: [M][K] bf16 hi/lo,  B: [N][K] bf16 hi/lo,  C: [M][N] fp32
// BM=BN=128, BK=32, 512 threads (16 warps, 8x2), warp tile 16x64
// ---------------------------------------------------------------------------
#define PAD 40
#define ARR_BYTES (128 * PAD * 2)         // 10240 bytes per array
#define STAGE_BYTES (4 * ARR_BYTES)       // AsHi, AsLo, BsHi, BsLo
#define GEMM_SMEM_BYTES (2 * STAGE_BYTES) // 81920

#define CP16(dst_u32, src_ptr) \
    asm volatile("cp.async.cg.shared.global [%0], [%1], 16;\n" \
                 :: "r"(dst_u32), "l"(src_ptr))

__device__ __forceinline__ void mma16816(float* c, const unsigned* a, const unsigned* b) {
    asm volatile(
        "mma.sync.aligned.m16n8k16.row.col.f32.bf16.bf16.f32 "
        "{%0,%1,%2,%3}, {%4,%5,%6,%7}, {%8,%9}, {%0,%1,%2,%3};\n"
        : "+f"(c[0]), "+f"(c[1]), "+f"(c[2]), "+f"(c[3])
        : "r"(a[0]), "r"(a[1]), "r"(a[2]), "r"(a[3]), "r"(b[0]), "r"(b[1]));
}

__device__ __forceinline__ void ldsm4(unsigned* r, unsigned addr) {
    asm volatile("ldmatrix.sync.aligned.m8n8.x4.shared.b16 {%0,%1,%2,%3}, [%4];\n"
                 : "=r"(r[0]), "=r"(r[1]), "=r"(r[2]), "=r"(r[3]) : "r"(addr));
}

template <bool RESID>
__global__ __launch_bounds__(512, 2)
void gemm_mma(const ushort_t* __restrict__ Ahi, const ushort_t* __restrict__ Alo,
              const ushort_t* __restrict__ Bhi, const ushort_t* __restrict__ Blo,
              const float* __restrict__ bias, const float* __restrict__ resid,
              float* __restrict__ C, int M, int N, int K) {
    extern __shared__ ushort_t smem[];
    unsigned smem_u32 = (unsigned)__cvta_generic_to_shared((void*)smem);

    int tid = threadIdx.x;
    int lane = tid & 31;
    int wid = tid >> 5;               // 0..15
    int warp_m = wid & 7;             // 8 warps along M (16 rows each)
    int warp_n = wid >> 3;            // 2 warps along N (64 cols each)
    int row0 = blockIdx.y * 128;
    int col0 = blockIdx.x * 128;
    int m0 = warp_m * 16;
    int nb = warp_n * 64;

    // acc[nh][4], nh = 0..7 (8 cols each)
    float acc[8][4];
#pragma unroll
    for (int j = 0; j < 8; j++)
#pragma unroll
        for (int l = 0; l < 4; l++) acc[j][l] = 0.0f;

    // per-thread ldmatrix offsets (bytes, within stage)
    // A: row = m0 + (lane&15), col halves = (lane>>4)*8
    unsigned offA = (unsigned)(((m0 + (lane & 15)) * PAD + (lane >> 4) * 8) * 2);
    // B: n = nb + (lane&7) + ((lane>>4)<<3), k halves = ((lane>>3)&1)*8
    unsigned offB = (unsigned)(((nb + (lane & 7) + ((lane >> 4) << 3)) * PAD
                                + ((lane >> 3) & 1) * 8) * 2);

    // loader: 512 threads, each does 4 cp.async (one per array)
    int r_ld = tid >> 2;
    int c8 = (tid & 3) * 8;
    unsigned soff = (unsigned)((r_ld * PAD + c8) * 2);

    int T = K / 32;
#pragma unroll 1
    for (int t = 0; t < T + 1; t++) {
        if (t < T) {
            int k0 = t * 32;
            unsigned sbase = smem_u32 + (t & 1) * STAGE_BYTES;
            size_t ga = (size_t)(row0 + r_ld) * K + k0 + c8;
            size_t gb = (size_t)(col0 + r_ld) * K + k0 + c8;
            CP16(sbase + soff, Ahi + ga);
            CP16(sbase + ARR_BYTES + soff, Alo + ga);
            CP16(sbase + 2 * ARR_BYTES + soff, Bhi + gb);
            CP16(sbase + 3 * ARR_BYTES + soff, Blo + gb);
            asm volatile("cp.async.commit_group;\n");
        }
        if (t == 0) continue;
        if (t < T) asm volatile("cp.async.wait_group 1;\n");
        else       asm volatile("cp.async.wait_group 0;\n");
        __syncthreads();

        unsigned sbase = smem_u32 + ((t - 1) & 1) * STAGE_BYTES;
#pragma unroll
        for (int ks = 0; ks < 2; ks++) {
            unsigned ksb = ks * 32;   // 16 halves = 32 bytes
            unsigned a_hi[4], a_lo[4];
            ldsm4(a_hi, sbase + offA + ksb);
            ldsm4(a_lo, sbase + ARR_BYTES + offA + ksb);
#pragma unroll
            for (int g = 0; g < 4; g++) {
                unsigned bh[4], bl[4];
                unsigned go = (unsigned)(g * 16 * PAD * 2);
                ldsm4(bh, sbase + 2 * ARR_BYTES + offB + go + ksb);
                ldsm4(bl, sbase + 3 * ARR_BYTES + offB + go + ksb);
                mma16816(acc[g * 2],     a_hi, bh);
                mma16816(acc[g * 2],     a_hi, bl);
                mma16816(acc[g * 2],     a_lo, bh);
                mma16816(acc[g * 2 + 1], a_hi, bh + 2);
                mma16816(acc[g * 2 + 1], a_hi, bl + 2);
                mma16816(acc[g * 2 + 1], a_lo, bh + 2);
            }
        }
        __syncthreads();
    }

    // ---- epilogue: bias (+resid) ----
    int r0 = row0 + m0 + (lane >> 2);
    int r1 = r0 + 8;
#pragma unroll
    for (int nh = 0; nh < 8; nh++) {
        int cc = col0 + nb + nh * 8 + (lane & 3) * 2;
        float b0 = bias[cc], b1 = bias[cc + 1];
        float2 v0, v1;
        v0.x = acc[nh][0] + b0; v0.y = acc[nh][1] + b1;
        v1.x = acc[nh][2] + b0; v1.y = acc[nh][3] + b1;
        if (RESID) {
            float2 rs0 = *(const float2*)&resid[(size_t)r0 * N + cc];
            float2 rs1 = *(const float2*)&resid[(size_t)r1 * N + cc];
            v0.x += rs0.x; v0.y += rs0.y;
            v1.x += rs1.x; v1.y += rs1.y;
        }
        *(float2*)&C[(size_t)r0 * N + cc] = v0;
        *(float2*)&C[(size_t)r1 * N + cc] = v1;
    }
}

// ---------------------------------------------------------------------------
// Kernel 3: RoPE in place on q (heads 0..31) and k (heads 32..39)
// ---------------------------------------------------------------------------
__global__ void rope_kernel(const float* __restrict__ cosT,
                            const float* __restrict__ sinT) {
    int idx = blockIdx.x * blockDim.x + threadIdx.x;
    if (idx >= T_SEQ * 40 * 32) return;
    int d = idx & 31;
    int rest = idx >> 5;
    int head = rest % 40;
    int t = rest / 40;
    float c = cosT[t * 32 + d];
    float s = sinT[t * 32 + d];
    float* p = g_qkv + (size_t)t * QKVD + head * 64 + d;
    float x1 = p[0];
    float x2 = p[32];
    p[0] = x1 * c - x2 * s;
    p[32] = x2 * c + x1 * s;
}

// ---------------------------------------------------------------------------
// Kernel 4: sliding-window GQA attention with sinks; emits bf16 hi/lo
// ---------------------------------------------------------------------------
#define TQ 16
#define SM_Q 0
#define SM_K (64 * 65)
#define SM_V (SM_K + 144 * 65)
#define SM_S (SM_V + 144 * 68)
#define SM_TOTAL (SM_S + 64 * 145)

__global__ void attn_kernel(const float* __restrict__ sinks) {
    extern __shared__ float sm[];
    float* Qs = sm + SM_Q;
    float* Ks = sm + SM_K;
    float* Vs = sm + SM_V;
    float* Ss = sm + SM_S;

    int qb = blockIdx.x;
    int n = blockIdx.y;
    int qstart = qb * TQ;
    int kmin = qstart - SW; if (kmin < 0) kmin = 0;
    int nkey = qstart + TQ - kmin;
    int tid = threadIdx.x;

    for (int v = tid; v < 64 * 16; v += 256) {
        int row = v >> 4;
        int d4 = (v & 15) * 4;
        int m = row >> 4, qi = row & 15;
        float4 q = *(const float4*)&g_qkv[(size_t)(qstart + qi) * QKVD + n * 256 + m * 64 + d4];
        Qs[row * 65 + d4 + 0] = q.x;
        Qs[row * 65 + d4 + 1] = q.y;
        Qs[row * 65 + d4 + 2] = q.z;
        Qs[row * 65 + d4 + 3] = q.w;
    }
    for (int v = tid; v < nkey * 16; v += 256) {
        int r = v >> 4;
        int d4 = (v & 15) * 4;
        int kg = kmin + r;
        float4 kk = *(const float4*)&g_qkv[(size_t)kg * QKVD + 2048 + n * 64 + d4];
        Ks[r * 65 + d4 + 0] = kk.x;
        Ks[r * 65 + d4 + 1] = kk.y;
        Ks[r * 65 + d4 + 2] = kk.z;
        Ks[r * 65 + d4 + 3] = kk.w;
        float4 vv = *(const float4*)&g_qkv[(size_t)kg * QKVD + 2560 + n * 64 + d4];
        *(float4*)&Vs[r * 68 + d4] = vv;
    }
    __syncthreads();

    int tx = tid & 15, ty = tid >> 4;
    int r0 = ty * 4;
    int k0 = tx * 9;

    float acc[4][9];
#pragma unroll
    for (int i = 0; i < 4; i++)
#pragma unroll
        for (int j = 0; j < 9; j++) acc[i][j] = 0.0f;
#pragma unroll 8
    for (int d = 0; d < 64; d++) {
        float qa[4], kb[9];
#pragma unroll
        for (int i = 0; i < 4; i++) qa[i] = Qs[(r0 + i) * 65 + d];
#pragma unroll
        for (int j = 0; j < 9; j++) kb[j] = Ks[(k0 + j) * 65 + d];
#pragma unroll
        for (int i = 0; i < 4; i++)
#pragma unroll
            for (int j = 0; j < 9; j++) acc[i][j] = fmaf(qa[i], kb[j], acc[i][j]);
    }
#pragma unroll
    for (int j = 0; j < 9; j++) {
        int key = k0 + j;
        if (key < nkey) {
            int kg = kmin + key;
#pragma unroll
            for (int i = 0; i < 4; i++) {
                int row = r0 + i;
                int qg = qstart + (row & 15);
                float s;
                if (kg <= qg && (qg - kg) <= SW) s = acc[i][j] * 0.125f;
                else s = -1e30f;
                Ss[row * 145 + key] = s;
            }
        }
    }
    __syncthreads();

    int wid = tid >> 5, lane = tid & 31;
    for (int rr = 0; rr < 8; rr++) {
        int row = wid * 8 + rr;
        int m = row >> 4;
        float s0 = sinks[n * QM + m];
        float vmax = -1e30f;
        for (int k = lane; k < nkey; k += 32) vmax = fmaxf(vmax, Ss[row * 145 + k]);
#pragma unroll
        for (int off = 16; off > 0; off >>= 1)
            vmax = fmaxf(vmax, __shfl_xor_sync(0xffffffffu, vmax, off));
        vmax = fmaxf(vmax, s0);
        float vsum = 0.0f;
        for (int k = lane; k < nkey; k += 32) {
            float e = __expf(Ss[row * 145 + k] - vmax);
            Ss[row * 145 + k] = e;
            vsum += e;
        }
#pragma unroll
        for (int off = 16; off > 0; off >>= 1)
            vsum += __shfl_xor_sync(0xffffffffu, vsum, off);
        vsum += __expf(s0 - vmax);
        float inv = 1.0f / vsum;
        for (int k = lane; k < nkey; k += 32) Ss[row * 145 + k] *= inv;
    }
    __syncthreads();

    int c0 = tx * 4;
    float o[4][4];
#pragma unroll
    for (int i = 0; i < 4; i++)
#pragma unroll
        for (int j = 0; j < 4; j++) o[i][j] = 0.0f;
    for (int k = 0; k < nkey; k++) {
        float4 vv = *(float4*)&Vs[k * 68 + c0];
        float ws[4];
#pragma unroll
        for (int i = 0; i < 4; i++) ws[i] = Ss[(r0 + i) * 145 + k];
#pragma unroll
        for (int i = 0; i < 4; i++) {
            o[i][0] = fmaf(ws[i], vv.x, o[i][0]);
            o[i][1] = fmaf(ws[i], vv.y, o[i][1]);
            o[i][2] = fmaf(ws[i], vv.z, o[i][2]);
            o[i][3] = fmaf(ws[i], vv.w, o[i][3]);
        }
    }
#pragma unroll
    for (int i = 0; i < 4; i++) {
        int row = r0 + i;
        int t = qstart + (row & 15);
        int m = row >> 4;
        size_t col = (size_t)t * H_DIM + n * 256 + m * 64 + c0;
        ushort_t h[4], l[4];
#pragma unroll
        for (int j = 0; j < 4; j++) {
            h[j] = bf_bits(o[i][j]);
            l[j] = bf_bits(o[i][j] - bf_val(h[j]));
        }
        *(uint2*)&g_ahi[col] = make_uint2((unsigned)h[0] | ((unsigned)h[1] << 16),
                                          (unsigned)h[2] | ((unsigned)h[3] << 16));
        *(uint2*)&g_alo[col] = make_uint2((unsigned)l[0] | ((unsigned)l[1] << 16),
                                          (unsigned)l[2] | ((unsigned)l[3] << 16));
    }
}

// ---------------------------------------------------------------------------
// Launch
// ---------------------------------------------------------------------------
extern "C" void kernel_launch(void* const* d_in, const int* in_sizes, int n_in,
                              void* d_out, int out_size) {
    const float* x       = (const float*)d_in[0];
    const float* scale   = (const float*)d_in[1];
    const float* sinks   = (const float*)d_in[2];
    const float* qkvW    = (const float*)d_in[3];
    const float* qkvB    = (const float*)d_in[4];
    const float* outW    = (const float*)d_in[5];
    const float* outB    = (const float*)d_in[6];
    const float* cosT    = (const float*)d_in[7];
    const float* sinT    = (const float*)d_in[8];
    float* out = (float*)d_out;

    ushort_t *p_nhi, *p_nlo, *p_ahi, *p_alo;
    ushort_t *p_wqkv_hi, *p_wqkv_lo, *p_wout_hi, *p_wout_lo;
    cudaGetSymbolAddress((void**)&p_nhi, g_nhi);
    cudaGetSymbolAddress((void**)&p_nlo, g_nlo);
    cudaGetSymbolAddress((void**)&p_ahi, g_ahi);
    cudaGetSymbolAddress((void**)&p_alo, g_alo);
    cudaGetSymbolAddress((void**)&p_wqkv_hi, g_wqkv_hi);
    cudaGetSymbolAddress((void**)&p_wqkv_lo, g_wqkv_lo);
    cudaGetSymbolAddress((void**)&p_wout_hi, g_wout_hi);
    cudaGetSymbolAddress((void**)&p_wout_lo, g_wout_lo);
    float* p_qkv;
    cudaGetSymbolAddress((void**)&p_qkv, g_qkv);

    // 0. split+transpose weights
    {
        dim3 blk(32, 8);
        split_transpose<<<dim3(QKVD / 32, H_DIM / 32), blk>>>(qkvW, p_wqkv_hi, p_wqkv_lo,
                                                              H_DIM, QKVD);
        split_transpose<<<dim3(H_DIM / 32, H_DIM / 32), blk>>>(outW, p_wout_hi, p_wout_lo,
                                                               H_DIM, H_DIM);
    }

    // 1. RMSNorm -> bf16 hi/lo
    rmsnorm_kernel<<<T_SEQ, 256>>>(x, scale, p_nhi, p_nlo);

    // 2. QKV GEMM
    {
        cudaFuncSetAttribute(gemm_mma<false>, cudaFuncAttributeMaxDynamicSharedMemorySize,
                             GEMM_SMEM_BYTES);
        dim3 grid(QKVD / 128, T_SEQ / 128);
        gemm_mma<false><<<grid, 512, GEMM_SMEM_BYTES>>>(p_nhi, p_nlo, p_wqkv_hi, p_wqkv_lo,
                                                        qkvB, nullptr, p_qkv,
                                                        T_SEQ, QKVD, H_DIM);
    }

    // 3. RoPE on q + k
    {
        int total = T_SEQ * 40 * 32;
        rope_kernel<<<(total + 255) / 256, 256>>>(cosT, sinT);
    }

    // 4. Attention -> bf16 hi/lo
    {
        cudaFuncSetAttribute(attn_kernel, cudaFuncAttributeMaxDynamicSharedMemorySize,
                             SM_TOTAL * (int)sizeof(float));
        dim3 grid(T_SEQ / TQ, NKV);
        attn_kernel<<<grid, 256, SM_TOTAL * sizeof(float)>>>(sinks);
    }

    // 5. Output projection + residual
    {
        cudaFuncSetAttribute(gemm_mma<true>, cudaFuncAttributeMaxDynamicSharedMemorySize,
                             GEMM_SMEM_BYTES);
        dim3 grid(H_DIM / 128, T_SEQ / 128);
        gemm_mma<true><<<grid, 512, GEMM_SMEM_BYTES>>>(p_ahi, p_alo, p_wout_hi, p_wout_lo,
                                                       outB, x, out,
                                                       T_SEQ, H_DIM, H_DIM);
    }
}

// round 8
// speedup vs baseline: 2.2419x; 1.0594x over previous
#include <cuda_runtime.h>
#include <cuda_bf16.h>
#include <math.h>

// Problem constants
#define T_SEQ 2048
#define H_DIM 2048
#define NH 32
#define NKV 8
#define HD 64
#define SW 128
#define QM 4              // NH / NKV
#define QKVD 3072         // HD*(NH+2*NKV)
#define EPS 1e-5f

typedef unsigned short ushort_t;

// Scratch (device globals; no allocation allowed)
__device__ float g_qkv[T_SEQ * QKVD];
__device__ ushort_t g_nhi[T_SEQ * H_DIM];      // rmsnorm out, hi bf16
__device__ ushort_t g_nlo[T_SEQ * H_DIM];      // rmsnorm out, lo bf16
__device__ ushort_t g_ahi[T_SEQ * H_DIM];      // attn out, hi bf16
__device__ ushort_t g_alo[T_SEQ * H_DIM];      // attn out, lo bf16
__device__ ushort_t g_wqkv_hi[QKVD * H_DIM];   // qkv weight, [N][K] bf16 hi
__device__ ushort_t g_wqkv_lo[QKVD * H_DIM];
__device__ ushort_t g_wout_hi[H_DIM * H_DIM];  // out weight, [N][K] bf16 hi
__device__ ushort_t g_wout_lo[H_DIM * H_DIM];

__device__ __forceinline__ ushort_t bf_bits(float x) {
    __nv_bfloat16 h = __float2bfloat16(x);
    return *reinterpret_cast<ushort_t*>(&h);
}
__device__ __forceinline__ float bf_val(ushort_t u) {
    __nv_bfloat16 h = *reinterpret_cast<__nv_bfloat16*>(&u);
    return __bfloat162float(h);
}

// ---------------------------------------------------------------------------
// Kernel 0: weight split + transpose.  W[K][N] fp32 -> Whi/Wlo[N][K] bf16
// ---------------------------------------------------------------------------
__global__ void split_transpose(const float* __restrict__ W,
                                ushort_t* __restrict__ Whi,
                                ushort_t* __restrict__ Wlo, int K, int N) {
    __shared__ float t[32][33];
    int n0 = blockIdx.x * 32, k0 = blockIdx.y * 32;
    int tx = threadIdx.x, ty = threadIdx.y;  // 32 x 8
#pragma unroll
    for (int i = 0; i < 4; i++)
        t[ty + i * 8][tx] = W[(size_t)(k0 + ty + i * 8) * N + n0 + tx];
    __syncthreads();
#pragma unroll
    for (int i = 0; i < 4; i++) {
        int n = ty + i * 8;
        float x = t[tx][n];
        ushort_t h = bf_bits(x);
        ushort_t l = bf_bits(x - bf_val(h));
        Whi[(size_t)(n0 + n) * K + k0 + tx] = h;
        Wlo[(size_t)(n0 + n) * K + k0 + tx] = l;
    }
}

// ---------------------------------------------------------------------------
// Kernel 1: RMSNorm per row, emits bf16 hi/lo directly
// ---------------------------------------------------------------------------
__global__ void rmsnorm_kernel(const float* __restrict__ x,
                               const float* __restrict__ scale,
                               ushort_t* __restrict__ ohi,
                               ushort_t* __restrict__ olo) {
    __shared__ float red[256];
    int row = blockIdx.x;
    int tid = threadIdx.x;
    const float4* xr = (const float4*)(x + (size_t)row * H_DIM);
    float4 v0 = xr[tid];
    float4 v1 = xr[tid + 256];
    float ss = v0.x * v0.x + v0.y * v0.y + v0.z * v0.z + v0.w * v0.w
             + v1.x * v1.x + v1.y * v1.y + v1.z * v1.z + v1.w * v1.w;
    red[tid] = ss;
    __syncthreads();
    for (int s = 128; s > 0; s >>= 1) {
        if (tid < s) red[tid] += red[tid + s];
        __syncthreads();
    }
    float inv = rsqrtf(red[0] * (1.0f / H_DIM) + EPS);
    const float4* sc = (const float4*)scale;
    float4 s0 = sc[tid], s1 = sc[tid + 256];
    float o[8];
    o[0] = v0.x * inv * s0.x; o[1] = v0.y * inv * s0.y;
    o[2] = v0.z * inv * s0.z; o[3] = v0.w * inv * s0.w;
    o[4] = v1.x * inv * s1.x; o[5] = v1.y * inv * s1.y;
    o[6] = v1.z * inv * s1.z; o[7] = v1.w * inv * s1.w;
    ushort_t h[8], l[8];
#pragma unroll
    for (int i = 0; i < 8; i++) {
        h[i] = bf_bits(o[i]);
        l[i] = bf_bits(o[i] - bf_val(h[i]));
    }
    size_t base = (size_t)row * H_DIM;
    uint2 h0 = make_uint2((unsigned)h[0] | ((unsigned)h[1] << 16),
                          (unsigned)h[2] | ((unsigned)h[3] << 16));
    uint2 h1 = make_uint2((unsigned)h[4] | ((unsigned)h[5] << 16),
                          (unsigned)h[6] | ((unsigned)h[7] << 16));
    uint2 l0 = make_uint2((unsigned)l[0] | ((unsigned)l[1] << 16),
                          (unsigned)l[2] | ((unsigned)l[3] << 16));
    uint2 l1 = make_uint2((unsigned)l[4] | ((unsigned)l[5] << 16),
                          (unsigned)l[6] | ((unsigned)l[7] << 16));
    *(uint2*)&ohi[base + tid * 4] = h0;
    *(uint2*)&ohi[base + 1024 + tid * 4] = h1;
    *(uint2*)&olo[base + tid * 4] = l0;
    *(uint2*)&olo[base + 1024 + tid * 4] = l1;
}

// ---------------------------------------------------------------------------
// Tensor-core GEMM, 3xBF16 split, pre-split operands, K-major B, cp.async
// double buffering, ldmatrix fragment loads.
// A: [M][K] bf16 hi/lo,  B: [N][K] bf16 hi/lo,  C: [M][N] fp32
// BM=BN=128, BK=32, 512 threads (16 warps, 8x2), warp tile 16x64
// ---------------------------------------------------------------------------
#define PAD 40
#define ARR_BYTES (128 * PAD * 2)         // 10240 bytes per array
#define STAGE_BYTES (4 * ARR_BYTES)       // AsHi, AsLo, BsHi, BsLo
#define GEMM_SMEM_BYTES (2 * STAGE_BYTES) // 81920

#define CP16(dst_u32, src_ptr) \
    asm volatile("cp.async.cg.shared.global [%0], [%1], 16;\n" \
                 :: "r"(dst_u32), "l"(src_ptr))

__device__ __forceinline__ void mma16816(float* c, const unsigned* a, const unsigned* b) {
    asm volatile(
        "mma.sync.aligned.m16n8k16.row.col.f32.bf16.bf16.f32 "
        "{%0,%1,%2,%3}, {%4,%5,%6,%7}, {%8,%9}, {%0,%1,%2,%3};\n"
        : "+f"(c[0]), "+f"(c[1]), "+f"(c[2]), "+f"(c[3])
        : "r"(a[0]), "r"(a[1]), "r"(a[2]), "r"(a[3]), "r"(b[0]), "r"(b[1]));
}

__device__ __forceinline__ void ldsm4(unsigned* r, unsigned addr) {
    asm volatile("ldmatrix.sync.aligned.m8n8.x4.shared.b16 {%0,%1,%2,%3}, [%4];\n"
                 : "=r"(r[0]), "=r"(r[1]), "=r"(r[2]), "=r"(r[3]) : "r"(addr));
}

template <bool RESID>
__global__ __launch_bounds__(512, 2)
void gemm_mma(const ushort_t* __restrict__ Ahi, const ushort_t* __restrict__ Alo,
              const ushort_t* __restrict__ Bhi, const ushort_t* __restrict__ Blo,
              const float* __restrict__ bias, const float* __restrict__ resid,
              float* __restrict__ C, int M, int N, int K) {
    extern __shared__ ushort_t smem[];
    unsigned smem_u32 = (unsigned)__cvta_generic_to_shared((void*)smem);

    int tid = threadIdx.x;
    int lane = tid & 31;
    int wid = tid >> 5;               // 0..15
    int warp_m = wid & 7;             // 8 warps along M (16 rows each)
    int warp_n = wid >> 3;            // 2 warps along N (64 cols each)
    int row0 = blockIdx.y * 128;
    int col0 = blockIdx.x * 128;
    int m0 = warp_m * 16;
    int nb = warp_n * 64;

    // acc[nh][4], nh = 0..7 (8 cols each)
    float acc[8][4];
#pragma unroll
    for (int j = 0; j < 8; j++)
#pragma unroll
        for (int l = 0; l < 4; l++) acc[j][l] = 0.0f;

    // per-thread ldmatrix offsets (bytes, within stage)
    unsigned offA = (unsigned)(((m0 + (lane & 15)) * PAD + (lane >> 4) * 8) * 2);
    unsigned offB = (unsigned)(((nb + (lane & 7) + ((lane >> 4) << 3)) * PAD
                                + ((lane >> 3) & 1) * 8) * 2);

    // loader: 512 threads, each does 4 cp.async (one per array)
    int r_ld = tid >> 2;
    int c8 = (tid & 3) * 8;
    unsigned soff = (unsigned)((r_ld * PAD + c8) * 2);

    int T = K / 32;
#pragma unroll 1
    for (int t = 0; t < T + 1; t++) {
        if (t < T) {
            int k0 = t * 32;
            unsigned sbase = smem_u32 + (t & 1) * STAGE_BYTES;
            size_t ga = (size_t)(row0 + r_ld) * K + k0 + c8;
            size_t gb = (size_t)(col0 + r_ld) * K + k0 + c8;
            CP16(sbase + soff, Ahi + ga);
            CP16(sbase + ARR_BYTES + soff, Alo + ga);
            CP16(sbase + 2 * ARR_BYTES + soff, Bhi + gb);
            CP16(sbase + 3 * ARR_BYTES + soff, Blo + gb);
            asm volatile("cp.async.commit_group;\n");
        }
        if (t == 0) continue;
        if (t < T) asm volatile("cp.async.wait_group 1;\n");
        else       asm volatile("cp.async.wait_group 0;\n");
        __syncthreads();

        unsigned sbase = smem_u32 + ((t - 1) & 1) * STAGE_BYTES;
#pragma unroll
        for (int ks = 0; ks < 2; ks++) {
            unsigned ksb = ks * 32;   // 16 halves = 32 bytes
            unsigned a_hi[4], a_lo[4];
            ldsm4(a_hi, sbase + offA + ksb);
            ldsm4(a_lo, sbase + ARR_BYTES + offA + ksb);
#pragma unroll
            for (int g = 0; g < 4; g++) {
                unsigned bh[4], bl[4];
                unsigned go = (unsigned)(g * 16 * PAD * 2);
                ldsm4(bh, sbase + 2 * ARR_BYTES + offB + go + ksb);
                ldsm4(bl, sbase + 3 * ARR_BYTES + offB + go + ksb);
                mma16816(acc[g * 2],     a_hi, bh);
                mma16816(acc[g * 2],     a_hi, bl);
                mma16816(acc[g * 2],     a_lo, bh);
                mma16816(acc[g * 2 + 1], a_hi, bh + 2);
                mma16816(acc[g * 2 + 1], a_hi, bl + 2);
                mma16816(acc[g * 2 + 1], a_lo, bh + 2);
            }
        }
        __syncthreads();
    }

    // ---- epilogue: bias (+resid) ----
    int r0 = row0 + m0 + (lane >> 2);
    int r1 = r0 + 8;
#pragma unroll
    for (int nh = 0; nh < 8; nh++) {
        int cc = col0 + nb + nh * 8 + (lane & 3) * 2;
        float b0 = bias[cc], b1 = bias[cc + 1];
        float2 v0, v1;
        v0.x = acc[nh][0] + b0; v0.y = acc[nh][1] + b1;
        v1.x = acc[nh][2] + b0; v1.y = acc[nh][3] + b1;
        if (RESID) {
            float2 rs0 = *(const float2*)&resid[(size_t)r0 * N + cc];
            float2 rs1 = *(const float2*)&resid[(size_t)r1 * N + cc];
            v0.x += rs0.x; v0.y += rs0.y;
            v1.x += rs1.x; v1.y += rs1.y;
        }
        *(float2*)&C[(size_t)r0 * N + cc] = v0;
        *(float2*)&C[(size_t)r1 * N + cc] = v1;
    }
}

// ---------------------------------------------------------------------------
// Kernel 3: RoPE in place on q (heads 0..31) and k (heads 32..39)
// ---------------------------------------------------------------------------
__global__ void rope_kernel(const float* __restrict__ cosT,
                            const float* __restrict__ sinT) {
    int idx = blockIdx.x * blockDim.x + threadIdx.x;
    if (idx >= T_SEQ * 40 * 32) return;
    int d = idx & 31;
    int rest = idx >> 5;
    int head = rest % 40;
    int t = rest / 40;
    float c = cosT[t * 32 + d];
    float s = sinT[t * 32 + d];
    float* p = g_qkv + (size_t)t * QKVD + head * 64 + d;
    float x1 = p[0];
    float x2 = p[32];
    p[0] = x1 * c - x2 * s;
    p[32] = x2 * c + x1 * s;
}

// ---------------------------------------------------------------------------
// Kernel 4: sliding-window GQA attention with sinks; emits bf16 hi/lo.
// Block = (16 queries) x (1 kv head, 4 q-heads), 256 threads.
// S matrix aliases the K tile (K dead after QK^T) -> 93.5KB smem, 2 CTA/SM.
// ---------------------------------------------------------------------------
#define TQ 16
#define QPAD 68
#define SSTR 148
#define SM_Q 0
#define SM_K (64 * QPAD)                 // 4352
#define SM_V (SM_K + 144 * QPAD)         // K/S region: 144*68 = 9792 floats
#define SM_TOTAL (SM_V + 144 * QPAD)     // 23936 floats = 95744 B

__global__ __launch_bounds__(256, 2)
void attn_kernel(const float* __restrict__ sinks) {
    extern __shared__ float sm[];
    float* Qs = sm + SM_Q;   // [64][68]  row = m*16+qi
    float* Ks = sm + SM_K;   // [144][68]
    float* Vs = sm + SM_V;   // [144][68]
    float* Ss = sm + SM_K;   // alias: [64][148] (<= 9792 floats)

    int qb = blockIdx.x;
    int n = blockIdx.y;
    int qstart = qb * TQ;
    int kmin = qstart - SW; if (kmin < 0) kmin = 0;
    int nkey = qstart + TQ - kmin;   // multiple of 16, <= 144
    int tid = threadIdx.x;

    for (int v = tid; v < 64 * 16; v += 256) {
        int row = v >> 4;
        int d4 = (v & 15) * 4;
        int m = row >> 4, qi = row & 15;
        float4 q = *(const float4*)&g_qkv[(size_t)(qstart + qi) * QKVD + n * 256 + m * 64 + d4];
        *(float4*)&Qs[row * QPAD + d4] = q;
    }
    for (int v = tid; v < nkey * 16; v += 256) {
        int r = v >> 4;
        int d4 = (v & 15) * 4;
        int kg = kmin + r;
        float4 kk = *(const float4*)&g_qkv[(size_t)kg * QKVD + 2048 + n * 64 + d4];
        *(float4*)&Ks[r * QPAD + d4] = kk;
        float4 vv = *(const float4*)&g_qkv[(size_t)kg * QKVD + 2560 + n * 64 + d4];
        *(float4*)&Vs[r * QPAD + d4] = vv;
    }
    __syncthreads();

    int tx = tid & 15, ty = tid >> 4;
    int r0 = ty * 4;
    int k0 = tx * 9;

    // S = Q @ K^T  (d unrolled x4 with float4 loads)
    float acc[4][9];
#pragma unroll
    for (int i = 0; i < 4; i++)
#pragma unroll
        for (int j = 0; j < 9; j++) acc[i][j] = 0.0f;
#pragma unroll 4
    for (int d = 0; d < 64; d += 4) {
        float4 qa[4], kb[9];
#pragma unroll
        for (int i = 0; i < 4; i++) qa[i] = *(const float4*)&Qs[(r0 + i) * QPAD + d];
#pragma unroll
        for (int j = 0; j < 9; j++) kb[j] = *(const float4*)&Ks[(k0 + j) * QPAD + d];
#pragma unroll
        for (int i = 0; i < 4; i++)
#pragma unroll
            for (int j = 0; j < 9; j++) {
                acc[i][j] = fmaf(qa[i].x, kb[j].x, acc[i][j]);
                acc[i][j] = fmaf(qa[i].y, kb[j].y, acc[i][j]);
                acc[i][j] = fmaf(qa[i].z, kb[j].z, acc[i][j]);
                acc[i][j] = fmaf(qa[i].w, kb[j].w, acc[i][j]);
            }
    }
    // all reads of Ks done before S (alias) is written
    __syncthreads();

#pragma unroll
    for (int j = 0; j < 9; j++) {
        int key = k0 + j;
        if (key < nkey) {
            int kg = kmin + key;
#pragma unroll
            for (int i = 0; i < 4; i++) {
                int row = r0 + i;
                int qg = qstart + (row & 15);
                float s;
                if (kg <= qg && (qg - kg) <= SW) s = acc[i][j] * 0.125f;
                else s = -1e30f;
                Ss[row * SSTR + key] = s;
            }
        }
    }
    __syncthreads();

    // softmax with sink: warp w handles rows w*8..w*8+7
    int wid = tid >> 5, lane = tid & 31;
    for (int rr = 0; rr < 8; rr++) {
        int row = wid * 8 + rr;
        int m = row >> 4;
        float s0 = sinks[n * QM + m];
        float vmax = -1e30f;
        for (int k = lane; k < nkey; k += 32) vmax = fmaxf(vmax, Ss[row * SSTR + k]);
#pragma unroll
        for (int off = 16; off > 0; off >>= 1)
            vmax = fmaxf(vmax, __shfl_xor_sync(0xffffffffu, vmax, off));
        vmax = fmaxf(vmax, s0);
        float vsum = 0.0f;
        for (int k = lane; k < nkey; k += 32) {
            float e = __expf(Ss[row * SSTR + k] - vmax);
            Ss[row * SSTR + k] = e;
            vsum += e;
        }
#pragma unroll
        for (int off = 16; off > 0; off >>= 1)
            vsum += __shfl_xor_sync(0xffffffffu, vsum, off);
        vsum += __expf(s0 - vmax);
        float inv = 1.0f / vsum;
        for (int k = lane; k < nkey; k += 32) Ss[row * SSTR + k] *= inv;
    }
    __syncthreads();

    // O = W @ V  (k unrolled x4, float4 S and V loads)
    int c0 = tx * 4;
    float o[4][4];
#pragma unroll
    for (int i = 0; i < 4; i++)
#pragma unroll
        for (int j = 0; j < 4; j++) o[i][j] = 0.0f;
    for (int k = 0; k < nkey; k += 4) {
        float4 ws[4];
#pragma unroll
        for (int i = 0; i < 4; i++) ws[i] = *(const float4*)&Ss[(r0 + i) * SSTR + k];
#pragma unroll
        for (int kk = 0; kk < 4; kk++) {
            float4 vv = *(const float4*)&Vs[(k + kk) * QPAD + c0];
            float w0 = (kk == 0) ? ws[0].x : (kk == 1) ? ws[0].y : (kk == 2) ? ws[0].z : ws[0].w;
            float w1 = (kk == 0) ? ws[1].x : (kk == 1) ? ws[1].y : (kk == 2) ? ws[1].z : ws[1].w;
            float w2 = (kk == 0) ? ws[2].x : (kk == 1) ? ws[2].y : (kk == 2) ? ws[2].z : ws[2].w;
            float w3 = (kk == 0) ? ws[3].x : (kk == 1) ? ws[3].y : (kk == 2) ? ws[3].z : ws[3].w;
            o[0][0] = fmaf(w0, vv.x, o[0][0]); o[0][1] = fmaf(w0, vv.y, o[0][1]);
            o[0][2] = fmaf(w0, vv.z, o[0][2]); o[0][3] = fmaf(w0, vv.w, o[0][3]);
            o[1][0] = fmaf(w1, vv.x, o[1][0]); o[1][1] = fmaf(w1, vv.y, o[1][1]);
            o[1][2] = fmaf(w1, vv.z, o[1][2]); o[1][3] = fmaf(w1, vv.w, o[1][3]);
            o[2][0] = fmaf(w2, vv.x, o[2][0]); o[2][1] = fmaf(w2, vv.y, o[2][1]);
            o[2][2] = fmaf(w2, vv.z, o[2][2]); o[2][3] = fmaf(w2, vv.w, o[2][3]);
            o[3][0] = fmaf(w3, vv.x, o[3][0]); o[3][1] = fmaf(w3, vv.y, o[3][1]);
            o[3][2] = fmaf(w3, vv.z, o[3][2]); o[3][3] = fmaf(w3, vv.w, o[3][3]);
        }
    }
#pragma unroll
    for (int i = 0; i < 4; i++) {
        int row = r0 + i;
        int t = qstart + (row & 15);
        int m = row >> 4;
        size_t col = (size_t)t * H_DIM + n * 256 + m * 64 + c0;
        ushort_t h[4], l[4];
#pragma unroll
        for (int j = 0; j < 4; j++) {
            h[j] = bf_bits(o[i][j]);
            l[j] = bf_bits(o[i][j] - bf_val(h[j]));
        }
        *(uint2*)&g_ahi[col] = make_uint2((unsigned)h[0] | ((unsigned)h[1] << 16),
                                          (unsigned)h[2] | ((unsigned)h[3] << 16));
        *(uint2*)&g_alo[col] = make_uint2((unsigned)l[0] | ((unsigned)l[1] << 16),
                                          (unsigned)l[2] | ((unsigned)l[3] << 16));
    }
}

// ---------------------------------------------------------------------------
// Launch
// ---------------------------------------------------------------------------
extern "C" void kernel_launch(void* const* d_in, const int* in_sizes, int n_in,
                              void* d_out, int out_size) {
    const float* x       = (const float*)d_in[0];
    const float* scale   = (const float*)d_in[1];
    const float* sinks   = (const float*)d_in[2];
    const float* qkvW    = (const float*)d_in[3];
    const float* qkvB    = (const float*)d_in[4];
    const float* outW    = (const float*)d_in[5];
    const float* outB    = (const float*)d_in[6];
    const float* cosT    = (const float*)d_in[7];
    const float* sinT    = (const float*)d_in[8];
    float* out = (float*)d_out;

    ushort_t *p_nhi, *p_nlo, *p_ahi, *p_alo;
    ushort_t *p_wqkv_hi, *p_wqkv_lo, *p_wout_hi, *p_wout_lo;
    cudaGetSymbolAddress((void**)&p_nhi, g_nhi);
    cudaGetSymbolAddress((void**)&p_nlo, g_nlo);
    cudaGetSymbolAddress((void**)&p_ahi, g_ahi);
    cudaGetSymbolAddress((void**)&p_alo, g_alo);
    cudaGetSymbolAddress((void**)&p_wqkv_hi, g_wqkv_hi);
    cudaGetSymbolAddress((void**)&p_wqkv_lo, g_wqkv_lo);
    cudaGetSymbolAddress((void**)&p_wout_hi, g_wout_hi);
    cudaGetSymbolAddress((void**)&p_wout_lo, g_wout_lo);
    float* p_qkv;
    cudaGetSymbolAddress((void**)&p_qkv, g_qkv);

    // 0. split+transpose weights
    {
        dim3 blk(32, 8);
        split_transpose<<<dim3(QKVD / 32, H_DIM / 32), blk>>>(qkvW, p_wqkv_hi, p_wqkv_lo,
                                                              H_DIM, QKVD);
        split_transpose<<<dim3(H_DIM / 32, H_DIM / 32), blk>>>(outW, p_wout_hi, p_wout_lo,
                                                               H_DIM, H_DIM);
    }

    // 1. RMSNorm -> bf16 hi/lo
    rmsnorm_kernel<<<T_SEQ, 256>>>(x, scale, p_nhi, p_nlo);

    // 2. QKV GEMM
    {
        cudaFuncSetAttribute(gemm_mma<false>, cudaFuncAttributeMaxDynamicSharedMemorySize,
                             GEMM_SMEM_BYTES);
        dim3 grid(QKVD / 128, T_SEQ / 128);
        gemm_mma<false><<<grid, 512, GEMM_SMEM_BYTES>>>(p_nhi, p_nlo, p_wqkv_hi, p_wqkv_lo,
                                                        qkvB, nullptr, p_qkv,
                                                        T_SEQ, QKVD, H_DIM);
    }

    // 3. RoPE on q + k
    {
        int total = T_SEQ * 40 * 32;
        rope_kernel<<<(total + 255) / 256, 256>>>(cosT, sinT);
    }

    // 4. Attention -> bf16 hi/lo
    {
        cudaFuncSetAttribute(attn_kernel, cudaFuncAttributeMaxDynamicSharedMemorySize,
                             SM_TOTAL * (int)sizeof(float));
        dim3 grid(T_SEQ / TQ, NKV);
        attn_kernel<<<grid, 256, SM_TOTAL * sizeof(float)>>>(sinks);
    }

    // 5. Output projection + residual
    {
        cudaFuncSetAttribute(gemm_mma<true>, cudaFuncAttributeMaxDynamicSharedMemorySize,
                             GEMM_SMEM_BYTES);
        dim3 grid(H_DIM / 128, T_SEQ / 128);
        gemm_mma<true><<<grid, 512, GEMM_SMEM_BYTES>>>(p_ahi, p_alo, p_wout_hi, p_wout_lo,
                                                       outB, x, out,
                                                       T_SEQ, H_DIM, H_DIM);
    }
}

// round 10
// speedup vs baseline: 2.8076x; 1.2523x over previous
#include <cuda_runtime.h>
#include <cuda_fp16.h>
#include <math.h>

// Problem constants
#define T_SEQ 2048
#define H_DIM 2048
#define NH 32
#define NKV 8
#define HD 64
#define SW 128
#define QM 4              // NH / NKV
#define QKVD 3072         // HD*(NH+2*NKV)
#define EPS 1e-5f

typedef unsigned short ushort_t;

// Scratch (device globals; no allocation allowed)
__device__ float g_qkv[T_SEQ * QKVD];
__device__ ushort_t g_nh[T_SEQ * H_DIM];       // rmsnorm out, fp16
__device__ ushort_t g_ah[T_SEQ * H_DIM];       // attn out, fp16
__device__ ushort_t g_wqkv_hi[QKVD * H_DIM];   // qkv weight, [N][K] fp16 hi
__device__ ushort_t g_wqkv_lo[QKVD * H_DIM];   // fp16 residual
__device__ ushort_t g_wout_hi[H_DIM * H_DIM];  // out weight, [N][K] fp16 hi
__device__ ushort_t g_wout_lo[H_DIM * H_DIM];

__device__ __forceinline__ ushort_t hf_bits(float x) {
    __half h = __float2half_rn(x);
    return *reinterpret_cast<ushort_t*>(&h);
}
__device__ __forceinline__ float hf_val(ushort_t u) {
    __half h = *reinterpret_cast<__half*>(&u);
    return __half2float(h);
}

// ---------------------------------------------------------------------------
// Kernel 0: weight split + transpose.  W[K][N] fp32 -> Whi/Wlo[N][K] fp16
// ---------------------------------------------------------------------------
__global__ void split_transpose(const float* __restrict__ W,
                                ushort_t* __restrict__ Whi,
                                ushort_t* __restrict__ Wlo, int K, int N) {
    __shared__ float t[32][33];
    int n0 = blockIdx.x * 32, k0 = blockIdx.y * 32;
    int tx = threadIdx.x, ty = threadIdx.y;  // 32 x 8
#pragma unroll
    for (int i = 0; i < 4; i++)
        t[ty + i * 8][tx] = W[(size_t)(k0 + ty + i * 8) * N + n0 + tx];
    __syncthreads();
#pragma unroll
    for (int i = 0; i < 4; i++) {
        int n = ty + i * 8;
        float x = t[tx][n];
        ushort_t h = hf_bits(x);
        ushort_t l = hf_bits(x - hf_val(h));
        Whi[(size_t)(n0 + n) * K + k0 + tx] = h;
        Wlo[(size_t)(n0 + n) * K + k0 + tx] = l;
    }
}

// ---------------------------------------------------------------------------
// Kernel 1: RMSNorm per row, emits fp16
// ---------------------------------------------------------------------------
__global__ void rmsnorm_kernel(const float* __restrict__ x,
                               const float* __restrict__ scale,
                               ushort_t* __restrict__ oh) {
    __shared__ float red[256];
    int row = blockIdx.x;
    int tid = threadIdx.x;
    const float4* xr = (const float4*)(x + (size_t)row * H_DIM);
    float4 v0 = xr[tid];
    float4 v1 = xr[tid + 256];
    float ss = v0.x * v0.x + v0.y * v0.y + v0.z * v0.z + v0.w * v0.w
             + v1.x * v1.x + v1.y * v1.y + v1.z * v1.z + v1.w * v1.w;
    red[tid] = ss;
    __syncthreads();
    for (int s = 128; s > 0; s >>= 1) {
        if (tid < s) red[tid] += red[tid + s];
        __syncthreads();
    }
    float inv = rsqrtf(red[0] * (1.0f / H_DIM) + EPS);
    const float4* sc = (const float4*)scale;
    float4 s0 = sc[tid], s1 = sc[tid + 256];
    float o[8];
    o[0] = v0.x * inv * s0.x; o[1] = v0.y * inv * s0.y;
    o[2] = v0.z * inv * s0.z; o[3] = v0.w * inv * s0.w;
    o[4] = v1.x * inv * s1.x; o[5] = v1.y * inv * s1.y;
    o[6] = v1.z * inv * s1.z; o[7] = v1.w * inv * s1.w;
    ushort_t h[8];
#pragma unroll
    for (int i = 0; i < 8; i++) h[i] = hf_bits(o[i]);
    size_t base = (size_t)row * H_DIM;
    *(uint2*)&oh[base + tid * 4] =
        make_uint2((unsigned)h[0] | ((unsigned)h[1] << 16),
                   (unsigned)h[2] | ((unsigned)h[3] << 16));
    *(uint2*)&oh[base + 1024 + tid * 4] =
        make_uint2((unsigned)h[4] | ((unsigned)h[5] << 16),
                   (unsigned)h[6] | ((unsigned)h[7] << 16));
}

// ---------------------------------------------------------------------------
// Tensor-core GEMM, 2xFP16 scheme: C = A @ (Bhi+Blo)^T + bias (+resid)
// A: [M][K] fp16,  B: [N][K] fp16 hi/lo,  C: [M][N] fp32
// BM=BN=128, BK=32, 512 threads (16 warps, 8x2), warp tile 16x64
// cp.async double buffering + ldmatrix.
// ---------------------------------------------------------------------------
#define PAD 40
#define ARR_BYTES (128 * PAD * 2)         // 10240 bytes per array
#define STAGE_BYTES (3 * ARR_BYTES)       // A, BHi, BLo
#define GEMM_SMEM_BYTES (2 * STAGE_BYTES) // 61440

#define CP16(dst_u32, src_ptr) \
    asm volatile("cp.async.cg.shared.global [%0], [%1], 16;\n" \
                 :: "r"(dst_u32), "l"(src_ptr))

__device__ __forceinline__ void mma16816(float* c, const unsigned* a, const unsigned* b) {
    asm volatile(
        "mma.sync.aligned.m16n8k16.row.col.f32.f16.f16.f32 "
        "{%0,%1,%2,%3}, {%4,%5,%6,%7}, {%8,%9}, {%0,%1,%2,%3};\n"
        : "+f"(c[0]), "+f"(c[1]), "+f"(c[2]), "+f"(c[3])
        : "r"(a[0]), "r"(a[1]), "r"(a[2]), "r"(a[3]), "r"(b[0]), "r"(b[1]));
}

__device__ __forceinline__ void ldsm4(unsigned* r, unsigned addr) {
    asm volatile("ldmatrix.sync.aligned.m8n8.x4.shared.b16 {%0,%1,%2,%3}, [%4];\n"
                 : "=r"(r[0]), "=r"(r[1]), "=r"(r[2]), "=r"(r[3]) : "r"(addr));
}

template <bool RESID>
__global__ __launch_bounds__(512, 2)
void gemm_mma(const ushort_t* __restrict__ A,
              const ushort_t* __restrict__ Bhi, const ushort_t* __restrict__ Blo,
              const float* __restrict__ bias, const float* __restrict__ resid,
              float* __restrict__ C, int M, int N, int K) {
    extern __shared__ ushort_t smem[];
    unsigned smem_u32 = (unsigned)__cvta_generic_to_shared((void*)smem);

    int tid = threadIdx.x;
    int lane = tid & 31;
    int wid = tid >> 5;               // 0..15
    int warp_m = wid & 7;             // 8 warps along M (16 rows each)
    int warp_n = wid >> 3;            // 2 warps along N (64 cols each)
    int row0 = blockIdx.y * 128;
    int col0 = blockIdx.x * 128;
    int m0 = warp_m * 16;
    int nb = warp_n * 64;

    float acc[8][4];
#pragma unroll
    for (int j = 0; j < 8; j++)
#pragma unroll
        for (int l = 0; l < 4; l++) acc[j][l] = 0.0f;

    unsigned offA = (unsigned)(((m0 + (lane & 15)) * PAD + (lane >> 4) * 8) * 2);
    unsigned offB = (unsigned)(((nb + (lane & 7) + ((lane >> 4) << 3)) * PAD
                                + ((lane >> 3) & 1) * 8) * 2);

    // loader: 512 threads, each does 3 cp.async (one per array)
    int r_ld = tid >> 2;
    int c8 = (tid & 3) * 8;
    unsigned soff = (unsigned)((r_ld * PAD + c8) * 2);

    int T = K / 32;
#pragma unroll 1
    for (int t = 0; t < T + 1; t++) {
        if (t < T) {
            int k0 = t * 32;
            unsigned sbase = smem_u32 + (t & 1) * STAGE_BYTES;
            size_t ga = (size_t)(row0 + r_ld) * K + k0 + c8;
            size_t gb = (size_t)(col0 + r_ld) * K + k0 + c8;
            CP16(sbase + soff, A + ga);
            CP16(sbase + ARR_BYTES + soff, Bhi + gb);
            CP16(sbase + 2 * ARR_BYTES + soff, Blo + gb);
            asm volatile("cp.async.commit_group;\n");
        }
        if (t == 0) continue;
        if (t < T) asm volatile("cp.async.wait_group 1;\n");
        else       asm volatile("cp.async.wait_group 0;\n");
        __syncthreads();

        unsigned sbase = smem_u32 + ((t - 1) & 1) * STAGE_BYTES;
#pragma unroll
        for (int ks = 0; ks < 2; ks++) {
            unsigned ksb = ks * 32;
            unsigned a[4];
            ldsm4(a, sbase + offA + ksb);
#pragma unroll
            for (int g = 0; g < 4; g++) {
                unsigned bh[4], bl[4];
                unsigned go = (unsigned)(g * 16 * PAD * 2);
                ldsm4(bh, sbase + ARR_BYTES + offB + go + ksb);
                ldsm4(bl, sbase + 2 * ARR_BYTES + offB + go + ksb);
                mma16816(acc[g * 2],     a, bh);
                mma16816(acc[g * 2],     a, bl);
                mma16816(acc[g * 2 + 1], a, bh + 2);
                mma16816(acc[g * 2 + 1], a, bl + 2);
            }
        }
        __syncthreads();
    }

    // ---- epilogue: bias (+resid) ----
    int r0 = row0 + m0 + (lane >> 2);
    int r1 = r0 + 8;
#pragma unroll
    for (int nh = 0; nh < 8; nh++) {
        int cc = col0 + nb + nh * 8 + (lane & 3) * 2;
        float b0 = bias[cc], b1 = bias[cc + 1];
        float2 v0, v1;
        v0.x = acc[nh][0] + b0; v0.y = acc[nh][1] + b1;
        v1.x = acc[nh][2] + b0; v1.y = acc[nh][3] + b1;
        if (RESID) {
            float2 rs0 = *(const float2*)&resid[(size_t)r0 * N + cc];
            float2 rs1 = *(const float2*)&resid[(size_t)r1 * N + cc];
            v0.x += rs0.x; v0.y += rs0.y;
            v1.x += rs1.x; v1.y += rs1.y;
        }
        *(float2*)&C[(size_t)r0 * N + cc] = v0;
        *(float2*)&C[(size_t)r1 * N + cc] = v1;
    }
}

// ---------------------------------------------------------------------------
// Kernel 3: RoPE in place on q (heads 0..31) and k (heads 32..39)
// ---------------------------------------------------------------------------
__global__ void rope_kernel(const float* __restrict__ cosT,
                            const float* __restrict__ sinT) {
    int idx = blockIdx.x * blockDim.x + threadIdx.x;
    if (idx >= T_SEQ * 40 * 32) return;
    int d = idx & 31;
    int rest = idx >> 5;
    int head = rest % 40;
    int t = rest / 40;
    float c = cosT[t * 32 + d];
    float s = sinT[t * 32 + d];
    float* p = g_qkv + (size_t)t * QKVD + head * 64 + d;
    float x1 = p[0];
    float x2 = p[32];
    p[0] = x1 * c - x2 * s;
    p[32] = x2 * c + x1 * s;
}

// ---------------------------------------------------------------------------
// Kernel 4: sliding-window GQA attention with sinks; emits fp16.
// Block = (16 queries) x (1 kv head, 4 q-heads), 256 threads.
// S matrix aliases the K tile -> ~93.5KB smem, 2 CTA/SM.
// ---------------------------------------------------------------------------
#define TQ 16
#define QPAD 68
#define SSTR 148
#define SM_Q 0
#define SM_K (64 * QPAD)
#define SM_V (SM_K + 144 * QPAD)
#define SM_TOTAL (SM_V + 144 * QPAD)

__global__ __launch_bounds__(256, 2)
void attn_kernel(const float* __restrict__ sinks) {
    extern __shared__ float sm[];
    float* Qs = sm + SM_Q;   // [64][68]
    float* Ks = sm + SM_K;   // [144][68]
    float* Vs = sm + SM_V;   // [144][68]
    float* Ss = sm + SM_K;   // alias: [64][148]

    int qb = blockIdx.x;
    int n = blockIdx.y;
    int qstart = qb * TQ;
    int kmin = qstart - SW; if (kmin < 0) kmin = 0;
    int nkey = qstart + TQ - kmin;   // multiple of 16, <= 144
    int tid = threadIdx.x;

    for (int v = tid; v < 64 * 16; v += 256) {
        int row = v >> 4;
        int d4 = (v & 15) * 4;
        int m = row >> 4, qi = row & 15;
        float4 q = *(const float4*)&g_qkv[(size_t)(qstart + qi) * QKVD + n * 256 + m * 64 + d4];
        *(float4*)&Qs[row * QPAD + d4] = q;
    }
    for (int v = tid; v < nkey * 16; v += 256) {
        int r = v >> 4;
        int d4 = (v & 15) * 4;
        int kg = kmin + r;
        float4 kk = *(const float4*)&g_qkv[(size_t)kg * QKVD + 2048 + n * 64 + d4];
        *(float4*)&Ks[r * QPAD + d4] = kk;
        float4 vv = *(const float4*)&g_qkv[(size_t)kg * QKVD + 2560 + n * 64 + d4];
        *(float4*)&Vs[r * QPAD + d4] = vv;
    }
    __syncthreads();

    int tx = tid & 15, ty = tid >> 4;
    int r0 = ty * 4;
    int k0 = tx * 9;

    float acc[4][9];
#pragma unroll
    for (int i = 0; i < 4; i++)
#pragma unroll
        for (int j = 0; j < 9; j++) acc[i][j] = 0.0f;
#pragma unroll 4
    for (int d = 0; d < 64; d += 4) {
        float4 qa[4], kb[9];
#pragma unroll
        for (int i = 0; i < 4; i++) qa[i] = *(const float4*)&Qs[(r0 + i) * QPAD + d];
#pragma unroll
        for (int j = 0; j < 9; j++) kb[j] = *(const float4*)&Ks[(k0 + j) * QPAD + d];
#pragma unroll
        for (int i = 0; i < 4; i++)
#pragma unroll
            for (int j = 0; j < 9; j++) {
                acc[i][j] = fmaf(qa[i].x, kb[j].x, acc[i][j]);
                acc[i][j] = fmaf(qa[i].y, kb[j].y, acc[i][j]);
                acc[i][j] = fmaf(qa[i].z, kb[j].z, acc[i][j]);
                acc[i][j] = fmaf(qa[i].w, kb[j].w, acc[i][j]);
            }
    }
    __syncthreads();   // all Ks reads done before S alias written

#pragma unroll
    for (int j = 0; j < 9; j++) {
        int key = k0 + j;
        if (key < nkey) {
            int kg = kmin + key;
#pragma unroll
            for (int i = 0; i < 4; i++) {
                int row = r0 + i;
                int qg = qstart + (row & 15);
                float s;
                if (kg <= qg && (qg - kg) <= SW) s = acc[i][j] * 0.125f;
                else s = -1e30f;
                Ss[row * SSTR + key] = s;
            }
        }
    }
    __syncthreads();

    int wid = tid >> 5, lane = tid & 31;
    for (int rr = 0; rr < 8; rr++) {
        int row = wid * 8 + rr;
        int m = row >> 4;
        float s0 = sinks[n * QM + m];
        float vmax = -1e30f;
        for (int k = lane; k < nkey; k += 32) vmax = fmaxf(vmax, Ss[row * SSTR + k]);
#pragma unroll
        for (int off = 16; off > 0; off >>= 1)
            vmax = fmaxf(vmax, __shfl_xor_sync(0xffffffffu, vmax, off));
        vmax = fmaxf(vmax, s0);
        float vsum = 0.0f;
        for (int k = lane; k < nkey; k += 32) {
            float e = __expf(Ss[row * SSTR + k] - vmax);
            Ss[row * SSTR + k] = e;
            vsum += e;
        }
#pragma unroll
        for (int off = 16; off > 0; off >>= 1)
            vsum += __shfl_xor_sync(0xffffffffu, vsum, off);
        vsum += __expf(s0 - vmax);
        float inv = 1.0f / vsum;
        for (int k = lane; k < nkey; k += 32) Ss[row * SSTR + k] *= inv;
    }
    __syncthreads();

    int c0 = tx * 4;
    float o[4][4];
#pragma unroll
    for (int i = 0; i < 4; i++)
#pragma unroll
        for (int j = 0; j < 4; j++) o[i][j] = 0.0f;
    for (int k = 0; k < nkey; k += 4) {
        float4 ws[4];
#pragma unroll
        for (int i = 0; i < 4; i++) ws[i] = *(const float4*)&Ss[(r0 + i) * SSTR + k];
#pragma unroll
        for (int kk = 0; kk < 4; kk++) {
            float4 vv = *(const float4*)&Vs[(k + kk) * QPAD + c0];
            float w0 = (kk == 0) ? ws[0].x : (kk == 1) ? ws[0].y : (kk == 2) ? ws[0].z : ws[0].w;
            float w1 = (kk == 0) ? ws[1].x : (kk == 1) ? ws[1].y : (kk == 2) ? ws[1].z : ws[1].w;
            float w2 = (kk == 0) ? ws[2].x : (kk == 1) ? ws[2].y : (kk == 2) ? ws[2].z : ws[2].w;
            float w3 = (kk == 0) ? ws[3].x : (kk == 1) ? ws[3].y : (kk == 2) ? ws[3].z : ws[3].w;
            o[0][0] = fmaf(w0, vv.x, o[0][0]); o[0][1] = fmaf(w0, vv.y, o[0][1]);
            o[0][2] = fmaf(w0, vv.z, o[0][2]); o[0][3] = fmaf(w0, vv.w, o[0][3]);
            o[1][0] = fmaf(w1, vv.x, o[1][0]); o[1][1] = fmaf(w1, vv.y, o[1][1]);
            o[1][2] = fmaf(w1, vv.z, o[1][2]); o[1][3] = fmaf(w1, vv.w, o[1][3]);
            o[2][0] = fmaf(w2, vv.x, o[2][0]); o[2][1] = fmaf(w2, vv.y, o[2][1]);
            o[2][2] = fmaf(w2, vv.z, o[2][2]); o[2][3] = fmaf(w2, vv.w, o[2][3]);
            o[3][0] = fmaf(w3, vv.x, o[3][0]); o[3][1] = fmaf(w3, vv.y, o[3][1]);
            o[3][2] = fmaf(w3, vv.z, o[3][2]); o[3][3] = fmaf(w3, vv.w, o[3][3]);
        }
    }
#pragma unroll
    for (int i = 0; i < 4; i++) {
        int row = r0 + i;
        int t = qstart + (row & 15);
        int m = row >> 4;
        size_t col = (size_t)t * H_DIM + n * 256 + m * 64 + c0;
        ushort_t h[4];
#pragma unroll
        for (int j = 0; j < 4; j++) h[j] = hf_bits(o[i][j]);
        *(uint2*)&g_ah[col] = make_uint2((unsigned)h[0] | ((unsigned)h[1] << 16),
                                         (unsigned)h[2] | ((unsigned)h[3] << 16));
    }
}

// ---------------------------------------------------------------------------
// Launch
// ---------------------------------------------------------------------------
extern "C" void kernel_launch(void* const* d_in, const int* in_sizes, int n_in,
                              void* d_out, int out_size) {
    const float* x       = (const float*)d_in[0];
    const float* scale   = (const float*)d_in[1];
    const float* sinks   = (const float*)d_in[2];
    const float* qkvW    = (const float*)d_in[3];
    const float* qkvB    = (const float*)d_in[4];
    const float* outW    = (const float*)d_in[5];
    const float* outB    = (const float*)d_in[6];
    const float* cosT    = (const float*)d_in[7];
    const float* sinT    = (const float*)d_in[8];
    float* out = (float*)d_out;

    ushort_t *p_nh, *p_ah;
    ushort_t *p_wqkv_hi, *p_wqkv_lo, *p_wout_hi, *p_wout_lo;
    cudaGetSymbolAddress((void**)&p_nh, g_nh);
    cudaGetSymbolAddress((void**)&p_ah, g_ah);
    cudaGetSymbolAddress((void**)&p_wqkv_hi, g_wqkv_hi);
    cudaGetSymbolAddress((void**)&p_wqkv_lo, g_wqkv_lo);
    cudaGetSymbolAddress((void**)&p_wout_hi, g_wout_hi);
    cudaGetSymbolAddress((void**)&p_wout_lo, g_wout_lo);
    float* p_qkv;
    cudaGetSymbolAddress((void**)&p_qkv, g_qkv);

    // 0. split+transpose weights (fp16 hi/lo)
    {
        dim3 blk(32, 8);
        split_transpose<<<dim3(QKVD / 32, H_DIM / 32), blk>>>(qkvW, p_wqkv_hi, p_wqkv_lo,
                                                              H_DIM, QKVD);
        split_transpose<<<dim3(H_DIM / 32, H_DIM / 32), blk>>>(outW, p_wout_hi, p_wout_lo,
                                                               H_DIM, H_DIM);
    }

    // 1. RMSNorm -> fp16
    rmsnorm_kernel<<<T_SEQ, 256>>>(x, scale, p_nh);

    // 2. QKV GEMM
    {
        cudaFuncSetAttribute(gemm_mma<false>, cudaFuncAttributeMaxDynamicSharedMemorySize,
                             GEMM_SMEM_BYTES);
        dim3 grid(QKVD / 128, T_SEQ / 128);
        gemm_mma<false><<<grid, 512, GEMM_SMEM_BYTES>>>(p_nh, p_wqkv_hi, p_wqkv_lo,
                                                        qkvB, nullptr, p_qkv,
                                                        T_SEQ, QKVD, H_DIM);
    }

    // 3. RoPE on q + k
    {
        int total = T_SEQ * 40 * 32;
        rope_kernel<<<(total + 255) / 256, 256>>>(cosT, sinT);
    }

    // 4. Attention -> fp16
    {
        cudaFuncSetAttribute(attn_kernel, cudaFuncAttributeMaxDynamicSharedMemorySize,
                             SM_TOTAL * (int)sizeof(float));
        dim3 grid(T_SEQ / TQ, NKV);
        attn_kernel<<<grid, 256, SM_TOTAL * sizeof(float)>>>(sinks);
    }

    // 5. Output projection + residual
    {
        cudaFuncSetAttribute(gemm_mma<true>, cudaFuncAttributeMaxDynamicSharedMemorySize,
                             GEMM_SMEM_BYTES);
        dim3 grid(H_DIM / 128, T_SEQ / 128);
        gemm_mma<true><<<grid, 512, GEMM_SMEM_BYTES>>>(p_ah, p_wout_hi, p_wout_lo,
                                                       outB, x, out,
                                                       T_SEQ, H_DIM, H_DIM);
    }
}

// round 11
// speedup vs baseline: 3.7897x; 1.3498x over previous
#include <cuda_runtime.h>
#include <cuda_fp16.h>
#include <math.h>

// Problem constants
#define T_SEQ 2048
#define H_DIM 2048
#define NH 32
#define NKV 8
#define HD 64
#define SW 128
#define QM 4              // NH / NKV
#define QKVD 3072         // HD*(NH+2*NKV)
#define EPS 1e-5f

typedef unsigned short ushort_t;

// Scratch (device globals; no allocation allowed)
__device__ float g_qkv[T_SEQ * QKVD];
__device__ ushort_t g_nh[T_SEQ * H_DIM];       // rmsnorm out, fp16
__device__ ushort_t g_ah[T_SEQ * H_DIM];       // attn out, fp16
__device__ ushort_t g_wqkv[QKVD * H_DIM];      // qkv weight, [N][K] fp16
__device__ ushort_t g_wout[H_DIM * H_DIM];     // out weight, [N][K] fp16

__device__ __forceinline__ ushort_t hf_bits(float x) {
    __half h = __float2half_rn(x);
    return *reinterpret_cast<ushort_t*>(&h);
}

// ---------------------------------------------------------------------------
// Kernel 0: weight transpose + fp16 convert.  W[K][N] fp32 -> W[N][K] fp16
// ---------------------------------------------------------------------------
__global__ void split_transpose(const float* __restrict__ W,
                                ushort_t* __restrict__ Wh, int K, int N) {
    __shared__ float t[32][33];
    int n0 = blockIdx.x * 32, k0 = blockIdx.y * 32;
    int tx = threadIdx.x, ty = threadIdx.y;  // 32 x 8
#pragma unroll
    for (int i = 0; i < 4; i++)
        t[ty + i * 8][tx] = W[(size_t)(k0 + ty + i * 8) * N + n0 + tx];
    __syncthreads();
#pragma unroll
    for (int i = 0; i < 4; i++) {
        int n = ty + i * 8;
        Wh[(size_t)(n0 + n) * K + k0 + tx] = hf_bits(t[tx][n]);
    }
}

// ---------------------------------------------------------------------------
// Kernel 1: RMSNorm per row, emits fp16
// ---------------------------------------------------------------------------
__global__ void rmsnorm_kernel(const float* __restrict__ x,
                               const float* __restrict__ scale,
                               ushort_t* __restrict__ oh) {
    __shared__ float red[256];
    int row = blockIdx.x;
    int tid = threadIdx.x;
    const float4* xr = (const float4*)(x + (size_t)row * H_DIM);
    float4 v0 = xr[tid];
    float4 v1 = xr[tid + 256];
    float ss = v0.x * v0.x + v0.y * v0.y + v0.z * v0.z + v0.w * v0.w
             + v1.x * v1.x + v1.y * v1.y + v1.z * v1.z + v1.w * v1.w;
    red[tid] = ss;
    __syncthreads();
    for (int s = 128; s > 0; s >>= 1) {
        if (tid < s) red[tid] += red[tid + s];
        __syncthreads();
    }
    float inv = rsqrtf(red[0] * (1.0f / H_DIM) + EPS);
    const float4* sc = (const float4*)scale;
    float4 s0 = sc[tid], s1 = sc[tid + 256];
    float o[8];
    o[0] = v0.x * inv * s0.x; o[1] = v0.y * inv * s0.y;
    o[2] = v0.z * inv * s0.z; o[3] = v0.w * inv * s0.w;
    o[4] = v1.x * inv * s1.x; o[5] = v1.y * inv * s1.y;
    o[6] = v1.z * inv * s1.z; o[7] = v1.w * inv * s1.w;
    ushort_t h[8];
#pragma unroll
    for (int i = 0; i < 8; i++) h[i] = hf_bits(o[i]);
    size_t base = (size_t)row * H_DIM;
    *(uint2*)&oh[base + tid * 4] =
        make_uint2((unsigned)h[0] | ((unsigned)h[1] << 16),
                   (unsigned)h[2] | ((unsigned)h[3] << 16));
    *(uint2*)&oh[base + 1024 + tid * 4] =
        make_uint2((unsigned)h[4] | ((unsigned)h[5] << 16),
                   (unsigned)h[6] | ((unsigned)h[7] << 16));
}

// ---------------------------------------------------------------------------
// Tensor-core fp16 GEMM: C = A @ B^T + bias (+resid)
// A: [M][K] fp16,  B: [N][K] fp16,  C: [M][N] fp32
// BM=BN=128, BK=32, 512 threads (16 warps, 8x2), warp tile 16x64
// cp.async double buffering + ldmatrix.
// ---------------------------------------------------------------------------
#define PAD 40
#define ARR_BYTES (128 * PAD * 2)         // 10240 bytes per array
#define STAGE_BYTES (2 * ARR_BYTES)       // A, B
#define GEMM_SMEM_BYTES (2 * STAGE_BYTES) // 40960

#define CP16(dst_u32, src_ptr) \
    asm volatile("cp.async.cg.shared.global [%0], [%1], 16;\n" \
                 :: "r"(dst_u32), "l"(src_ptr))

__device__ __forceinline__ void mma16816(float* c, const unsigned* a, const unsigned* b) {
    asm volatile(
        "mma.sync.aligned.m16n8k16.row.col.f32.f16.f16.f32 "
        "{%0,%1,%2,%3}, {%4,%5,%6,%7}, {%8,%9}, {%0,%1,%2,%3};\n"
        : "+f"(c[0]), "+f"(c[1]), "+f"(c[2]), "+f"(c[3])
        : "r"(a[0]), "r"(a[1]), "r"(a[2]), "r"(a[3]), "r"(b[0]), "r"(b[1]));
}

__device__ __forceinline__ void ldsm4(unsigned* r, unsigned addr) {
    asm volatile("ldmatrix.sync.aligned.m8n8.x4.shared.b16 {%0,%1,%2,%3}, [%4];\n"
                 : "=r"(r[0]), "=r"(r[1]), "=r"(r[2]), "=r"(r[3]) : "r"(addr));
}

template <bool RESID>
__global__ __launch_bounds__(512, 2)
void gemm_mma(const ushort_t* __restrict__ A, const ushort_t* __restrict__ B,
              const float* __restrict__ bias, const float* __restrict__ resid,
              float* __restrict__ C, int M, int N, int K) {
    extern __shared__ ushort_t smem[];
    unsigned smem_u32 = (unsigned)__cvta_generic_to_shared((void*)smem);

    int tid = threadIdx.x;
    int lane = tid & 31;
    int wid = tid >> 5;               // 0..15
    int warp_m = wid & 7;             // 8 warps along M (16 rows each)
    int warp_n = wid >> 3;            // 2 warps along N (64 cols each)
    int row0 = blockIdx.y * 128;
    int col0 = blockIdx.x * 128;
    int m0 = warp_m * 16;
    int nb = warp_n * 64;

    float acc[8][4];
#pragma unroll
    for (int j = 0; j < 8; j++)
#pragma unroll
        for (int l = 0; l < 4; l++) acc[j][l] = 0.0f;

    unsigned offA = (unsigned)(((m0 + (lane & 15)) * PAD + (lane >> 4) * 8) * 2);
    unsigned offB = (unsigned)(((nb + (lane & 7) + ((lane >> 4) << 3)) * PAD
                                + ((lane >> 3) & 1) * 8) * 2);

    // loader: 512 threads, each does 2 cp.async (one per array)
    int r_ld = tid >> 2;
    int c8 = (tid & 3) * 8;
    unsigned soff = (unsigned)((r_ld * PAD + c8) * 2);

    int T = K / 32;
#pragma unroll 1
    for (int t = 0; t < T + 1; t++) {
        if (t < T) {
            int k0 = t * 32;
            unsigned sbase = smem_u32 + (t & 1) * STAGE_BYTES;
            size_t ga = (size_t)(row0 + r_ld) * K + k0 + c8;
            size_t gb = (size_t)(col0 + r_ld) * K + k0 + c8;
            CP16(sbase + soff, A + ga);
            CP16(sbase + ARR_BYTES + soff, B + gb);
            asm volatile("cp.async.commit_group;\n");
        }
        if (t == 0) continue;
        if (t < T) asm volatile("cp.async.wait_group 1;\n");
        else       asm volatile("cp.async.wait_group 0;\n");
        __syncthreads();

        unsigned sbase = smem_u32 + ((t - 1) & 1) * STAGE_BYTES;
#pragma unroll
        for (int ks = 0; ks < 2; ks++) {
            unsigned ksb = ks * 32;
            unsigned a[4];
            ldsm4(a, sbase + offA + ksb);
#pragma unroll
            for (int g = 0; g < 4; g++) {
                unsigned b[4];
                unsigned go = (unsigned)(g * 16 * PAD * 2);
                ldsm4(b, sbase + ARR_BYTES + offB + go + ksb);
                mma16816(acc[g * 2],     a, b);
                mma16816(acc[g * 2 + 1], a, b + 2);
            }
        }
        __syncthreads();
    }

    // ---- epilogue: bias (+resid) ----
    int r0 = row0 + m0 + (lane >> 2);
    int r1 = r0 + 8;
#pragma unroll
    for (int nh = 0; nh < 8; nh++) {
        int cc = col0 + nb + nh * 8 + (lane & 3) * 2;
        float b0 = bias[cc], b1 = bias[cc + 1];
        float2 v0, v1;
        v0.x = acc[nh][0] + b0; v0.y = acc[nh][1] + b1;
        v1.x = acc[nh][2] + b0; v1.y = acc[nh][3] + b1;
        if (RESID) {
            float2 rs0 = *(const float2*)&resid[(size_t)r0 * N + cc];
            float2 rs1 = *(const float2*)&resid[(size_t)r1 * N + cc];
            v0.x += rs0.x; v0.y += rs0.y;
            v1.x += rs1.x; v1.y += rs1.y;
        }
        *(float2*)&C[(size_t)r0 * N + cc] = v0;
        *(float2*)&C[(size_t)r1 * N + cc] = v1;
    }
}

// ---------------------------------------------------------------------------
// Kernel 3: RoPE in place on q (heads 0..31) and k (heads 32..39)
// ---------------------------------------------------------------------------
__global__ void rope_kernel(const float* __restrict__ cosT,
                            const float* __restrict__ sinT) {
    int idx = blockIdx.x * blockDim.x + threadIdx.x;
    if (idx >= T_SEQ * 40 * 32) return;
    int d = idx & 31;
    int rest = idx >> 5;
    int head = rest % 40;
    int t = rest / 40;
    float c = cosT[t * 32 + d];
    float s = sinT[t * 32 + d];
    float* p = g_qkv + (size_t)t * QKVD + head * 64 + d;
    float x1 = p[0];
    float x2 = p[32];
    p[0] = x1 * c - x2 * s;
    p[32] = x2 * c + x1 * s;
}

// ---------------------------------------------------------------------------
// Kernel 4: sliding-window GQA attention with sinks; emits fp16.
// Block = (16 queries) x (1 kv head, 4 q-heads), 256 threads.
// S matrix aliases the K tile -> ~93.5KB smem, 2 CTA/SM.
// ---------------------------------------------------------------------------
#define TQ 16
#define QPAD 68
#define SSTR 148
#define SM_Q 0
#define SM_K (64 * QPAD)
#define SM_V (SM_K + 144 * QPAD)
#define SM_TOTAL (SM_V + 144 * QPAD)

__global__ __launch_bounds__(256, 2)
void attn_kernel(const float* __restrict__ sinks) {
    extern __shared__ float sm[];
    float* Qs = sm + SM_Q;   // [64][68]
    float* Ks = sm + SM_K;   // [144][68]
    float* Vs = sm + SM_V;   // [144][68]
    float* Ss = sm + SM_K;   // alias: [64][148]

    int qb = blockIdx.x;
    int n = blockIdx.y;
    int qstart = qb * TQ;
    int kmin = qstart - SW; if (kmin < 0) kmin = 0;
    int nkey = qstart + TQ - kmin;   // multiple of 16, <= 144
    int tid = threadIdx.x;

    for (int v = tid; v < 64 * 16; v += 256) {
        int row = v >> 4;
        int d4 = (v & 15) * 4;
        int m = row >> 4, qi = row & 15;
        float4 q = *(const float4*)&g_qkv[(size_t)(qstart + qi) * QKVD + n * 256 + m * 64 + d4];
        *(float4*)&Qs[row * QPAD + d4] = q;
    }
    for (int v = tid; v < nkey * 16; v += 256) {
        int r = v >> 4;
        int d4 = (v & 15) * 4;
        int kg = kmin + r;
        float4 kk = *(const float4*)&g_qkv[(size_t)kg * QKVD + 2048 + n * 64 + d4];
        *(float4*)&Ks[r * QPAD + d4] = kk;
        float4 vv = *(const float4*)&g_qkv[(size_t)kg * QKVD + 2560 + n * 64 + d4];
        *(float4*)&Vs[r * QPAD + d4] = vv;
    }
    __syncthreads();

    int tx = tid & 15, ty = tid >> 4;
    int r0 = ty * 4;
    int k0 = tx * 9;

    float acc[4][9];
#pragma unroll
    for (int i = 0; i < 4; i++)
#pragma unroll
        for (int j = 0; j < 9; j++) acc[i][j] = 0.0f;
#pragma unroll 4
    for (int d = 0; d < 64; d += 4) {
        float4 qa[4], kb[9];
#pragma unroll
        for (int i = 0; i < 4; i++) qa[i] = *(const float4*)&Qs[(r0 + i) * QPAD + d];
#pragma unroll
        for (int j = 0; j < 9; j++) kb[j] = *(const float4*)&Ks[(k0 + j) * QPAD + d];
#pragma unroll
        for (int i = 0; i < 4; i++)
#pragma unroll
            for (int j = 0; j < 9; j++) {
                acc[i][j] = fmaf(qa[i].x, kb[j].x, acc[i][j]);
                acc[i][j] = fmaf(qa[i].y, kb[j].y, acc[i][j]);
                acc[i][j] = fmaf(qa[i].z, kb[j].z, acc[i][j]);
                acc[i][j] = fmaf(qa[i].w, kb[j].w, acc[i][j]);
            }
    }
    __syncthreads();   // all Ks reads done before S alias written

#pragma unroll
    for (int j = 0; j < 9; j++) {
        int key = k0 + j;
        if (key < nkey) {
            int kg = kmin + key;
#pragma unroll
            for (int i = 0; i < 4; i++) {
                int row = r0 + i;
                int qg = qstart + (row & 15);
                float s;
                if (kg <= qg && (qg - kg) <= SW) s = acc[i][j] * 0.125f;
                else s = -1e30f;
                Ss[row * SSTR + key] = s;
            }
        }
    }
    __syncthreads();

    int wid = tid >> 5, lane = tid & 31;
    for (int rr = 0; rr < 8; rr++) {
        int row = wid * 8 + rr;
        int m = row >> 4;
        float s0 = sinks[n * QM + m];
        float vmax = -1e30f;
        for (int k = lane; k < nkey; k += 32) vmax = fmaxf(vmax, Ss[row * SSTR + k]);
#pragma unroll
        for (int off = 16; off > 0; off >>= 1)
            vmax = fmaxf(vmax, __shfl_xor_sync(0xffffffffu, vmax, off));
        vmax = fmaxf(vmax, s0);
        float vsum = 0.0f;
        for (int k = lane; k < nkey; k += 32) {
            float e = __expf(Ss[row * SSTR + k] - vmax);
            Ss[row * SSTR + k] = e;
            vsum += e;
        }
#pragma unroll
        for (int off = 16; off > 0; off >>= 1)
            vsum += __shfl_xor_sync(0xffffffffu, vsum, off);
        vsum += __expf(s0 - vmax);
        float inv = 1.0f / vsum;
        for (int k = lane; k < nkey; k += 32) Ss[row * SSTR + k] *= inv;
    }
    __syncthreads();

    int c0 = tx * 4;
    float o[4][4];
#pragma unroll
    for (int i = 0; i < 4; i++)
#pragma unroll
        for (int j = 0; j < 4; j++) o[i][j] = 0.0f;
    for (int k = 0; k < nkey; k += 4) {
        float4 ws[4];
#pragma unroll
        for (int i = 0; i < 4; i++) ws[i] = *(const float4*)&Ss[(r0 + i) * SSTR + k];
#pragma unroll
        for (int kk = 0; kk < 4; kk++) {
            float4 vv = *(const float4*)&Vs[(k + kk) * QPAD + c0];
            float w0 = (kk == 0) ? ws[0].x : (kk == 1) ? ws[0].y : (kk == 2) ? ws[0].z : ws[0].w;
            float w1 = (kk == 0) ? ws[1].x : (kk == 1) ? ws[1].y : (kk == 2) ? ws[1].z : ws[1].w;
            float w2 = (kk == 0) ? ws[2].x : (kk == 1) ? ws[2].y : (kk == 2) ? ws[2].z : ws[2].w;
            float w3 = (kk == 0) ? ws[3].x : (kk == 1) ? ws[3].y : (kk == 2) ? ws[3].z : ws[3].w;
            o[0][0] = fmaf(w0, vv.x, o[0][0]); o[0][1] = fmaf(w0, vv.y, o[0][1]);
            o[0][2] = fmaf(w0, vv.z, o[0][2]); o[0][3] = fmaf(w0, vv.w, o[0][3]);
            o[1][0] = fmaf(w1, vv.x, o[1][0]); o[1][1] = fmaf(w1, vv.y, o[1][1]);
            o[1][2] = fmaf(w1, vv.z, o[1][2]); o[1][3] = fmaf(w1, vv.w, o[1][3]);
            o[2][0] = fmaf(w2, vv.x, o[2][0]); o[2][1] = fmaf(w2, vv.y, o[2][1]);
            o[2][2] = fmaf(w2, vv.z, o[2][2]); o[2][3] = fmaf(w2, vv.w, o[2][3]);
            o[3][0] = fmaf(w3, vv.x, o[3][0]); o[3][1] = fmaf(w3, vv.y, o[3][1]);
            o[3][2] = fmaf(w3, vv.z, o[3][2]); o[3][3] = fmaf(w3, vv.w, o[3][3]);
        }
    }
#pragma unroll
    for (int i = 0; i < 4; i++) {
        int row = r0 + i;
        int t = qstart + (row & 15);
        int m = row >> 4;
        size_t col = (size_t)t * H_DIM + n * 256 + m * 64 + c0;
        ushort_t h[4];
#pragma unroll
        for (int j = 0; j < 4; j++) h[j] = hf_bits(o[i][j]);
        *(uint2*)&g_ah[col] = make_uint2((unsigned)h[0] | ((unsigned)h[1] << 16),
                                         (unsigned)h[2] | ((unsigned)h[3] << 16));
    }
}

// ---------------------------------------------------------------------------
// Launch
// ---------------------------------------------------------------------------
extern "C" void kernel_launch(void* const* d_in, const int* in_sizes, int n_in,
                              void* d_out, int out_size) {
    const float* x       = (const float*)d_in[0];
    const float* scale   = (const float*)d_in[1];
    const float* sinks   = (const float*)d_in[2];
    const float* qkvW    = (const float*)d_in[3];
    const float* qkvB    = (const float*)d_in[4];
    const float* outW    = (const float*)d_in[5];
    const float* outB    = (const float*)d_in[6];
    const float* cosT    = (const float*)d_in[7];
    const float* sinT    = (const float*)d_in[8];
    float* out = (float*)d_out;

    ushort_t *p_nh, *p_ah, *p_wqkv, *p_wout;
    cudaGetSymbolAddress((void**)&p_nh, g_nh);
    cudaGetSymbolAddress((void**)&p_ah, g_ah);
    cudaGetSymbolAddress((void**)&p_wqkv, g_wqkv);
    cudaGetSymbolAddress((void**)&p_wout, g_wout);
    float* p_qkv;
    cudaGetSymbolAddress((void**)&p_qkv, g_qkv);

    // 0. transpose + fp16 weights
    {
        dim3 blk(32, 8);
        split_transpose<<<dim3(QKVD / 32, H_DIM / 32), blk>>>(qkvW, p_wqkv, H_DIM, QKVD);
        split_transpose<<<dim3(H_DIM / 32, H_DIM / 32), blk>>>(outW, p_wout, H_DIM, H_DIM);
    }

    // 1. RMSNorm -> fp16
    rmsnorm_kernel<<<T_SEQ, 256>>>(x, scale, p_nh);

    // 2. QKV GEMM
    {
        cudaFuncSetAttribute(gemm_mma<false>, cudaFuncAttributeMaxDynamicSharedMemorySize,
                             GEMM_SMEM_BYTES);
        dim3 grid(QKVD / 128, T_SEQ / 128);
        gemm_mma<false><<<grid, 512, GEMM_SMEM_BYTES>>>(p_nh, p_wqkv,
                                                        qkvB, nullptr, p_qkv,
                                                        T_SEQ, QKVD, H_DIM);
    }

    // 3. RoPE on q + k
    {
        int total = T_SEQ * 40 * 32;
        rope_kernel<<<(total + 255) / 256, 256>>>(cosT, sinT);
    }

    // 4. Attention -> fp16
    {
        cudaFuncSetAttribute(attn_kernel, cudaFuncAttributeMaxDynamicSharedMemorySize,
                             SM_TOTAL * (int)sizeof(float));
        dim3 grid(T_SEQ / TQ, NKV);
        attn_kernel<<<grid, 256, SM_TOTAL * sizeof(float)>>>(sinks);
    }

    // 5. Output projection + residual
    {
        cudaFuncSetAttribute(gemm_mma<true>, cudaFuncAttributeMaxDynamicSharedMemorySize,
                             GEMM_SMEM_BYTES);
        dim3 grid(H_DIM / 128, T_SEQ / 128);
        gemm_mma<true><<<grid, 512, GEMM_SMEM_BYTES>>>(p_ah, p_wout,
                                                       outB, x, out,
                                                       T_SEQ, H_DIM, H_DIM);
    }
}